// round 4
// baseline (speedup 1.0000x reference)
#include <cuda_runtime.h>
#include <cuda_bf16.h>
#include <math.h>
#include <stdint.h>

#define BATCH 2
#define SEQ   2048
#define DIM   2048
#define NH    16
#define DH    128

// Scratch — __device__ globals per allocation rules.
__device__ float g_Q[BATCH * SEQ * DIM];
__device__ float g_K[BATCH * SEQ * DIM];
__device__ float g_V[BATCH * SEQ * DIM];
__device__ float g_A[BATCH * SEQ * DIM];

// ===========================================================================
// Helpers
// ===========================================================================
__device__ __forceinline__ uint32_t smem_u32(const void* p) {
    uint32_t a;
    asm("{ .reg .u64 t; cvta.to.shared.u64 t, %1; cvt.u32.u64 %0, t; }"
        : "=r"(a) : "l"(p));
    return a;
}

// fp32 -> bf16 hi + bf16 lo split, packed pairwise (x low half, y high half)
__device__ __forceinline__ void split2(float x, float y, uint32_t& h, uint32_t& l) {
    __nv_bfloat16 hx = __float2bfloat16_rn(x);
    __nv_bfloat16 hy = __float2bfloat16_rn(y);
    float rx = x - __bfloat162float(hx);
    float ry = y - __bfloat162float(hy);
    __nv_bfloat16 lx = __float2bfloat16_rn(rx);
    __nv_bfloat16 ly = __float2bfloat16_rn(ry);
    h = (uint32_t)__bfloat16_as_ushort(hx) | ((uint32_t)__bfloat16_as_ushort(hy) << 16);
    l = (uint32_t)__bfloat16_as_ushort(lx) | ((uint32_t)__bfloat16_as_ushort(ly) << 16);
}

__device__ __forceinline__ void ldsm_x4(uint32_t addr, uint32_t r[4]) {
    asm volatile("ldmatrix.sync.aligned.m8n8.x4.shared.b16 {%0,%1,%2,%3}, [%4];"
                 : "=r"(r[0]), "=r"(r[1]), "=r"(r[2]), "=r"(r[3]) : "r"(addr));
}

__device__ __forceinline__ void mma_bf16(float c[4], const uint32_t a[4],
                                         const uint32_t b0, const uint32_t b1) {
    asm volatile(
        "mma.sync.aligned.m16n8k16.row.col.f32.bf16.bf16.f32 "
        "{%0,%1,%2,%3}, {%4,%5,%6,%7}, {%8,%9}, {%0,%1,%2,%3};"
        : "+f"(c[0]), "+f"(c[1]), "+f"(c[2]), "+f"(c[3])
        : "r"(a[0]), "r"(a[1]), "r"(a[2]), "r"(a[3]), "r"(b0), "r"(b1));
}

// ===========================================================================
// Split-bf16 HMMA GEMM: C[M,N] = A[M,K] @ W[N,K]^T + bias
// CTA 128x128, BK=32, 8 warps (2x4), warp tile 64x32, 3-pass split-bf16.
// SMEM row stride 40 bf16 (80B) -> conflict-free ldmatrix.
// ===========================================================================
#define TM 128
#define TN 128
#define BK 32
#define RS 40                                  // smem row stride in bf16
#define TILE_B (128 * RS * 2)                  // 10240 B
#define OP_A_HI 0
#define OP_A_LO TILE_B
#define OP_W_HI (2 * TILE_B)
#define OP_W_LO (3 * TILE_B)
#define BUF_B   (4 * TILE_B)                   // 40960 B
#define GEMM_SMEM (2 * BUF_B)                  // 81920 B

__global__ __launch_bounds__(256, 1) void gemm_tc_kernel(
    const float* __restrict__ A, const float* __restrict__ W,
    const float* __restrict__ bias, float* __restrict__ C,
    int M, int N, int Kd)
{
    extern __shared__ char smem[];
    const uint32_t sbase = smem_u32(smem);
    const int tid  = threadIdx.x;
    const int wid  = tid >> 5;
    const int lane = tid & 31;
    const int wm   = wid >> 2;                 // 0..1
    const int wn   = wid & 3;                  // 0..3
    const int bm   = blockIdx.y * TM;
    const int bn   = blockIdx.x * TN;

    float acc[4][4][4];
    #pragma unroll
    for (int i = 0; i < 4; i++)
        #pragma unroll
        for (int j = 0; j < 4; j++)
            #pragma unroll
            for (int e = 0; e < 4; e++) acc[i][j][e] = 0.f;

    // Per-thread gmem coords (4 float4 each for A and W per chunk)
    int rrow[4], rcol[4];
    #pragma unroll
    for (int p = 0; p < 4; p++) {
        int v = tid + p * 256;
        rrow[p] = v >> 3;
        rcol[p] = (v & 7) * 4;
    }

    float4 ra[4], rw[4];

    // --- load chunk 0 ---
    #pragma unroll
    for (int p = 0; p < 4; p++) {
        ra[p] = *(const float4*)&A[(size_t)(bm + rrow[p]) * Kd + rcol[p]];
        rw[p] = *(const float4*)&W[(size_t)(bn + rrow[p]) * Kd + rcol[p]];
    }
    // --- store chunk 0 to buf 0 ---
    #pragma unroll
    for (int p = 0; p < 4; p++) {
        uint32_t off = (uint32_t)(rrow[p] * RS + rcol[p]) * 2;
        uint2 h, l;
        split2(ra[p].x, ra[p].y, h.x, l.x);
        split2(ra[p].z, ra[p].w, h.y, l.y);
        *(uint2*)(smem + OP_A_HI + off) = h;
        *(uint2*)(smem + OP_A_LO + off) = l;
        split2(rw[p].x, rw[p].y, h.x, l.x);
        split2(rw[p].z, rw[p].w, h.y, l.y);
        *(uint2*)(smem + OP_W_HI + off) = h;
        *(uint2*)(smem + OP_W_LO + off) = l;
    }
    __syncthreads();

    const int g = lane >> 3;                   // ldmatrix group 0..3
    const int r8 = lane & 7;

    const int nchunk = Kd / BK;                // 64
    for (int ch = 1; ch <= nchunk; ch++) {
        // Prefetch next chunk into registers (hidden under mma).
        if (ch < nchunk) {
            const int k0 = ch * BK;
            #pragma unroll
            for (int p = 0; p < 4; p++) {
                ra[p] = *(const float4*)&A[(size_t)(bm + rrow[p]) * Kd + k0 + rcol[p]];
                rw[p] = *(const float4*)&W[(size_t)(bn + rrow[p]) * Kd + k0 + rcol[p]];
            }
        }

        // MMA on buffer (ch-1)&1
        {
            const uint32_t buf = sbase + ((ch - 1) & 1) * BUF_B;
            #pragma unroll
            for (int ks = 0; ks < 2; ks++) {
                const int k0 = ks * 16;
                uint32_t ah[4][4], al[4][4];
                #pragma unroll
                for (int mt = 0; mt < 4; mt++) {
                    int row = wm * 64 + mt * 16 + r8 + (g & 1) * 8;
                    uint32_t off = (uint32_t)(row * RS + k0 + (g >> 1) * 8) * 2;
                    ldsm_x4(buf + OP_A_HI + off, ah[mt]);
                    ldsm_x4(buf + OP_A_LO + off, al[mt]);
                }
                uint32_t bh[2][4], bl[2][4];
                #pragma unroll
                for (int np = 0; np < 2; np++) {
                    int nrow = wn * 32 + np * 16 + r8 + (g >> 1) * 8;
                    uint32_t off = (uint32_t)(nrow * RS + k0 + (g & 1) * 8) * 2;
                    ldsm_x4(buf + OP_W_HI + off, bh[np]);
                    ldsm_x4(buf + OP_W_LO + off, bl[np]);
                }
                #pragma unroll
                for (int mt = 0; mt < 4; mt++) {
                    #pragma unroll
                    for (int nt = 0; nt < 4; nt++) {
                        const int np = nt >> 1, hf = (nt & 1) * 2;
                        mma_bf16(acc[mt][nt], ah[mt], bh[np][hf], bh[np][hf + 1]);
                        mma_bf16(acc[mt][nt], ah[mt], bl[np][hf], bl[np][hf + 1]);
                        mma_bf16(acc[mt][nt], al[mt], bh[np][hf], bh[np][hf + 1]);
                    }
                }
            }
        }
        __syncthreads();

        // Store prefetched chunk into buffer ch&1
        if (ch < nchunk) {
            char* bufp = smem + (ch & 1) * BUF_B;
            #pragma unroll
            for (int p = 0; p < 4; p++) {
                uint32_t off = (uint32_t)(rrow[p] * RS + rcol[p]) * 2;
                uint2 h, l;
                split2(ra[p].x, ra[p].y, h.x, l.x);
                split2(ra[p].z, ra[p].w, h.y, l.y);
                *(uint2*)(bufp + OP_A_HI + off) = h;
                *(uint2*)(bufp + OP_A_LO + off) = l;
                split2(rw[p].x, rw[p].y, h.x, l.x);
                split2(rw[p].z, rw[p].w, h.y, l.y);
                *(uint2*)(bufp + OP_W_HI + off) = h;
                *(uint2*)(bufp + OP_W_LO + off) = l;
            }
            __syncthreads();
        }
    }

    // Epilogue: accumulators -> C (+bias). Thread owns rows lane>>2 (+8),
    // cols (lane&3)*2,+1 within each 16x8 mma tile.
    #pragma unroll
    for (int nt = 0; nt < 4; nt++) {
        const int gcol = bn + wn * 32 + nt * 8 + (lane & 3) * 2;
        const float2 bv = *(const float2*)&bias[gcol];
        #pragma unroll
        for (int mt = 0; mt < 4; mt++) {
            const int grow = bm + wm * 64 + mt * 16 + (lane >> 2);
            float2 o0, o1;
            o0.x = acc[mt][nt][0] + bv.x;
            o0.y = acc[mt][nt][1] + bv.y;
            o1.x = acc[mt][nt][2] + bv.x;
            o1.y = acc[mt][nt][3] + bv.y;
            *(float2*)&C[(size_t)grow * N + gcol] = o0;
            *(float2*)&C[(size_t)(grow + 8) * N + gcol] = o1;
        }
    }
}

// ===========================================================================
// Flash attention (fp32, causal) — unchanged.
// ===========================================================================
#define FROWSTRIDE 132
#define FLASH_SMEM_FLOATS (3 * 64 * FROWSTRIDE + 64 * 64 + 3 * 64)
#define FLASH_SMEM_BYTES  (FLASH_SMEM_FLOATS * 4)

__global__ __launch_bounds__(256) void flash_kernel(
    const float* __restrict__ Q, const float* __restrict__ K,
    const float* __restrict__ V, const int* __restrict__ causal_ptr,
    float* __restrict__ O)
{
    extern __shared__ float sm[];
    float* Qs   = sm;
    float* Ks   = Qs + 64 * FROWSTRIDE;
    float* Vs   = Ks + 64 * FROWSTRIDE;
    float* Ps   = Vs + 64 * FROWSTRIDE;
    float* mrow = Ps + 64 * 64;
    float* lrow = mrow + 64;
    float* crow = lrow + 64;

    const int tid = threadIdx.x;
    const int tx  = tid & 15;
    const int ty  = tid >> 4;
    const int qt  = blockIdx.x;
    const int h   = blockIdx.y;
    const int b   = blockIdx.z;
    const int q0  = qt * 64;
    const size_t base = (size_t)b * SEQ * DIM + (size_t)h * DH;
    const int causal = *causal_ptr;
    const float scale = 0.08838834764831845f;

    #pragma unroll
    for (int p = 0; p < 8; p++) {
        int i  = (tid >> 5) + p * 8;
        int d4 = (tid & 31) * 4;
        *(float4*)&Qs[i * FROWSTRIDE + d4] =
            *(const float4*)&Q[base + (size_t)(q0 + i) * DIM + d4];
    }
    if (tid < 64) { mrow[tid] = -INFINITY; lrow[tid] = 0.f; }

    float acc[4][8];
    #pragma unroll
    for (int r = 0; r < 4; r++)
        #pragma unroll
        for (int c = 0; c < 8; c++) acc[r][c] = 0.f;

    const int nkt = causal ? (qt + 1) : (SEQ / 64);

    for (int kt = 0; kt < nkt; kt++) {
        const int k0 = kt * 64;
        __syncthreads();

        #pragma unroll
        for (int p = 0; p < 8; p++) {
            int i  = (tid >> 5) + p * 8;
            int d4 = (tid & 31) * 4;
            *(float4*)&Ks[i * FROWSTRIDE + d4] =
                *(const float4*)&K[base + (size_t)(k0 + i) * DIM + d4];
            *(float4*)&Vs[i * FROWSTRIDE + d4] =
                *(const float4*)&V[base + (size_t)(k0 + i) * DIM + d4];
        }
        __syncthreads();

        float cs[4][4];
        #pragma unroll
        for (int r = 0; r < 4; r++)
            #pragma unroll
            for (int s = 0; s < 4; s++) cs[r][s] = 0.f;

        #pragma unroll 4
        for (int d0 = 0; d0 < DH; d0 += 4) {
            float4 q4[4], k4[4];
            #pragma unroll
            for (int r = 0; r < 4; r++)
                q4[r] = *(const float4*)&Qs[(ty * 4 + r) * FROWSTRIDE + d0];
            #pragma unroll
            for (int s = 0; s < 4; s++)
                k4[s] = *(const float4*)&Ks[(tx * 4 + s) * FROWSTRIDE + d0];
            #pragma unroll
            for (int r = 0; r < 4; r++)
                #pragma unroll
                for (int s = 0; s < 4; s++)
                    cs[r][s] += q4[r].x * k4[s].x + q4[r].y * k4[s].y
                              + q4[r].z * k4[s].z + q4[r].w * k4[s].w;
        }

        #pragma unroll
        for (int r = 0; r < 4; r++) {
            int gq = q0 + ty * 4 + r;
            float4 o;
            float v0 = cs[r][0] * scale, v1 = cs[r][1] * scale;
            float v2 = cs[r][2] * scale, v3 = cs[r][3] * scale;
            int gk = k0 + tx * 4;
            o.x = (causal && (gk + 0) > gq) ? -INFINITY : v0;
            o.y = (causal && (gk + 1) > gq) ? -INFINITY : v1;
            o.z = (causal && (gk + 2) > gq) ? -INFINITY : v2;
            o.w = (causal && (gk + 3) > gq) ? -INFINITY : v3;
            *(float4*)&Ps[(ty * 4 + r) * 64 + tx * 4] = o;
        }
        __syncthreads();

        if (tid < 64) {
            float m_old = mrow[tid];
            float mx = m_old;
            float* row = &Ps[tid * 64];
            #pragma unroll 8
            for (int c = 0; c < 64; c++) mx = fmaxf(mx, row[c]);
            float corr = __expf(m_old - mx);
            float s = 0.f;
            #pragma unroll 8
            for (int c = 0; c < 64; c++) {
                float e = __expf(row[c] - mx);
                row[c] = e;
                s += e;
            }
            lrow[tid] = lrow[tid] * corr + s;
            mrow[tid] = mx;
            crow[tid] = corr;
        }
        __syncthreads();

        float cr[4];
        #pragma unroll
        for (int r = 0; r < 4; r++) cr[r] = crow[ty * 4 + r];
        #pragma unroll
        for (int r = 0; r < 4; r++)
            #pragma unroll
            for (int c = 0; c < 8; c++) acc[r][c] *= cr[r];

        #pragma unroll 4
        for (int kk = 0; kk < 64; kk++) {
            float pr[4];
            #pragma unroll
            for (int r = 0; r < 4; r++)
                pr[r] = Ps[(ty * 4 + r) * 64 + kk];
            float4 v0 = *(const float4*)&Vs[kk * FROWSTRIDE + tx * 8];
            float4 v1 = *(const float4*)&Vs[kk * FROWSTRIDE + tx * 8 + 4];
            #pragma unroll
            for (int r = 0; r < 4; r++) {
                acc[r][0] += pr[r] * v0.x; acc[r][1] += pr[r] * v0.y;
                acc[r][2] += pr[r] * v0.z; acc[r][3] += pr[r] * v0.w;
                acc[r][4] += pr[r] * v1.x; acc[r][5] += pr[r] * v1.y;
                acc[r][6] += pr[r] * v1.z; acc[r][7] += pr[r] * v1.w;
            }
        }
    }

    #pragma unroll
    for (int r = 0; r < 4; r++) {
        int i = ty * 4 + r;
        float inv = 1.f / lrow[i];
        float4 o0, o1;
        o0.x = acc[r][0] * inv; o0.y = acc[r][1] * inv;
        o0.z = acc[r][2] * inv; o0.w = acc[r][3] * inv;
        o1.x = acc[r][4] * inv; o1.y = acc[r][5] * inv;
        o1.z = acc[r][6] * inv; o1.w = acc[r][7] * inv;
        float* orow = &O[base + (size_t)(q0 + i) * DIM + tx * 8];
        *(float4*)&orow[0] = o0;
        *(float4*)&orow[4] = o1;
    }
}

// ===========================================================================
extern "C" void kernel_launch(void* const* d_in, const int* in_sizes, int n_in,
                              void* d_out, int out_size)
{
    const float* q      = (const float*)d_in[0];
    const float* k      = (const float*)d_in[1];
    const float* v      = (const float*)d_in[2];
    const float* Wq     = (const float*)d_in[3];
    const float* bq     = (const float*)d_in[4];
    const float* Wk     = (const float*)d_in[5];
    const float* bk     = (const float*)d_in[6];
    const float* Wv     = (const float*)d_in[7];
    const float* bv     = (const float*)d_in[8];
    const float* Wo     = (const float*)d_in[9];
    const float* bo     = (const float*)d_in[10];
    const int*   causal = (const int*)d_in[11];
    float* out = (float*)d_out;

    float *Qb, *Kb, *Vb, *Ab;
    cudaGetSymbolAddress((void**)&Qb, g_Q);
    cudaGetSymbolAddress((void**)&Kb, g_K);
    cudaGetSymbolAddress((void**)&Vb, g_V);
    cudaGetSymbolAddress((void**)&Ab, g_A);

    const int M = BATCH * SEQ;                   // 4096
    dim3 ggrid(DIM / TN, M / TM);                // (16, 32)

    cudaFuncSetAttribute(gemm_tc_kernel,
                         cudaFuncAttributeMaxDynamicSharedMemorySize, GEMM_SMEM);
    cudaFuncSetAttribute(flash_kernel,
                         cudaFuncAttributeMaxDynamicSharedMemorySize, FLASH_SMEM_BYTES);

    gemm_tc_kernel<<<ggrid, 256, GEMM_SMEM>>>(q, Wq, bq, Qb, M, DIM, DIM);
    gemm_tc_kernel<<<ggrid, 256, GEMM_SMEM>>>(k, Wk, bk, Kb, M, DIM, DIM);
    gemm_tc_kernel<<<ggrid, 256, GEMM_SMEM>>>(v, Wv, bv, Vb, M, DIM, DIM);

    dim3 fgrid(SEQ / 64, NH, BATCH);             // (32, 16, 2)
    flash_kernel<<<fgrid, 256, FLASH_SMEM_BYTES>>>(Qb, Kb, Vb, causal, Ab);

    gemm_tc_kernel<<<ggrid, 256, GEMM_SMEM>>>(Ab, Wo, bo, out, M, DIM, DIM);
}

// round 7
// speedup vs baseline: 1.1750x; 1.1750x over previous
#include <cuda_runtime.h>
#include <math.h>
#include <stdint.h>

#define BATCH 2
#define SEQ   2048
#define DIM   2048
#define NH    16
#define DH    128

// Scratch — __device__ globals per allocation rules.
__device__ float g_Q[BATCH * SEQ * DIM];
__device__ float g_K[BATCH * SEQ * DIM];
__device__ float g_V[BATCH * SEQ * DIM];
__device__ float g_A[BATCH * SEQ * DIM];

// ===========================================================================
// Packed fp32 (f32x2) helpers — base sm_100+ PTX, 2 FMA per issue.
// ===========================================================================
typedef unsigned long long u64t;

__device__ __forceinline__ u64t pack2(float x) {
    u64t r;
    asm("mov.b64 %0, {%1, %2};" : "=l"(r) : "f"(x), "f"(x));
    return r;
}
__device__ __forceinline__ void fma2(u64t& c, u64t a, u64t b) {
    asm("fma.rn.f32x2 %0, %1, %2, %0;" : "+l"(c) : "l"(a), "l"(b));
}
__device__ __forceinline__ u64t mul2(u64t a, u64t b) {
    u64t r;
    asm("mul.rn.f32x2 %0, %1, %2;" : "=l"(r) : "l"(a), "l"(b));
    return r;
}
__device__ __forceinline__ float lo32(u64t v) {
    return __uint_as_float((unsigned)v);
}
__device__ __forceinline__ float hi32(u64t v) {
    return __uint_as_float((unsigned)(v >> 32));
}

// ===========================================================================
// GEMM: C[M,N] = A[M,K] @ W[N,K]^T + bias[N]   (fp32, f32x2 inner loop)
// 128x128 tile, BK=16, 256 threads, 8x8 per-thread micro-tile (acc packed
// pairwise along n: 8x4 u64).
// ===========================================================================
__global__ __launch_bounds__(256) void gemm_f32x2_kernel(
    const float* __restrict__ A, const float* __restrict__ W,
    const float* __restrict__ bias, float* __restrict__ C,
    int M, int N, int Kd)
{
    __shared__ float As[16][132];   // [k][m]
    __shared__ float Bs[16][132];   // [k][n]

    const int tid = threadIdx.x;
    const int tx  = tid & 15;       // n (16)
    const int ty  = tid >> 4;       // m (16)
    const int bm  = blockIdx.y * 128;
    const int bn  = blockIdx.x * 128;

    u64t acc2[8][4] = {};           // zero bit-pattern == (0.f, 0.f)

    for (int k0 = 0; k0 < Kd; k0 += 16) {
        #pragma unroll
        for (int p = 0; p < 2; p++) {
            int v   = tid + p * 256;
            int row = v >> 2;
            int k4  = (v & 3) * 4;
            float4 a = *(const float4*)&A[(size_t)(bm + row) * Kd + k0 + k4];
            As[k4 + 0][row] = a.x; As[k4 + 1][row] = a.y;
            As[k4 + 2][row] = a.z; As[k4 + 3][row] = a.w;
            float4 b = *(const float4*)&W[(size_t)(bn + row) * Kd + k0 + k4];
            Bs[k4 + 0][row] = b.x; Bs[k4 + 1][row] = b.y;
            Bs[k4 + 2][row] = b.z; Bs[k4 + 3][row] = b.w;
        }
        __syncthreads();

        #pragma unroll
        for (int kk = 0; kk < 16; kk++) {
            float a8[8];
            *(float4*)&a8[0] = *(const float4*)&As[kk][ty * 8];
            *(float4*)&a8[4] = *(const float4*)&As[kk][ty * 8 + 4];
            ulonglong2 b01 = *(const ulonglong2*)&Bs[kk][tx * 8];
            ulonglong2 b23 = *(const ulonglong2*)&Bs[kk][tx * 8 + 4];
            u64t bp[4] = {b01.x, b01.y, b23.x, b23.y};
            #pragma unroll
            for (int i = 0; i < 8; i++) {
                u64t ad = pack2(a8[i]);
                fma2(acc2[i][0], ad, bp[0]);
                fma2(acc2[i][1], ad, bp[1]);
                fma2(acc2[i][2], ad, bp[2]);
                fma2(acc2[i][3], ad, bp[3]);
            }
        }
        __syncthreads();
    }

    float bj[8];
    #pragma unroll
    for (int j = 0; j < 8; j++) bj[j] = bias[bn + tx * 8 + j];

    #pragma unroll
    for (int i = 0; i < 8; i++) {
        int m = bm + ty * 8 + i;
        float4 o0, o1;
        o0.x = lo32(acc2[i][0]) + bj[0]; o0.y = hi32(acc2[i][0]) + bj[1];
        o0.z = lo32(acc2[i][1]) + bj[2]; o0.w = hi32(acc2[i][1]) + bj[3];
        o1.x = lo32(acc2[i][2]) + bj[4]; o1.y = hi32(acc2[i][2]) + bj[5];
        o1.z = lo32(acc2[i][3]) + bj[6]; o1.w = hi32(acc2[i][3]) + bj[7];
        float* crow = &C[(size_t)m * N + bn + tx * 8];
        *(float4*)&crow[0] = o0;
        *(float4*)&crow[4] = o1;
    }
}

// ===========================================================================
// Flash attention (fp32, causal) with f32x2 inner loops and parallel softmax.
// ===========================================================================
#define FROWSTRIDE 132
#define FLASH_SMEM_FLOATS (3 * 64 * FROWSTRIDE + 64 * 64 + 3 * 64)
#define FLASH_SMEM_BYTES  (FLASH_SMEM_FLOATS * 4)

__global__ __launch_bounds__(256) void flash_kernel(
    const float* __restrict__ Q, const float* __restrict__ K,
    const float* __restrict__ V, const int* __restrict__ causal_ptr,
    float* __restrict__ O)
{
    extern __shared__ float sm[];
    float* Qs   = sm;
    float* Ks   = Qs + 64 * FROWSTRIDE;
    float* Vs   = Ks + 64 * FROWSTRIDE;
    float* Ps   = Vs + 64 * FROWSTRIDE;
    float* mrow = Ps + 64 * 64;
    float* lrow = mrow + 64;
    float* crow = lrow + 64;

    const int tid = threadIdx.x;
    const int tx  = tid & 15;
    const int ty  = tid >> 4;
    const int qt  = blockIdx.x;
    const int h   = blockIdx.y;
    const int b   = blockIdx.z;
    const int q0  = qt * 64;
    const size_t base = (size_t)b * SEQ * DIM + (size_t)h * DH;
    const int causal = *causal_ptr;
    const float scale = 0.08838834764831845f;

    #pragma unroll
    for (int p = 0; p < 8; p++) {
        int i  = (tid >> 5) + p * 8;
        int d4 = (tid & 31) * 4;
        *(float4*)&Qs[i * FROWSTRIDE + d4] =
            *(const float4*)&Q[base + (size_t)(q0 + i) * DIM + d4];
    }
    if (tid < 64) { mrow[tid] = -INFINITY; lrow[tid] = 0.f; }

    u64t acc2[4][4] = {};           // packed pairs along output-d

    const int nkt = causal ? (qt + 1) : (SEQ / 64);

    for (int kt = 0; kt < nkt; kt++) {
        const int k0 = kt * 64;
        __syncthreads();

        #pragma unroll
        for (int p = 0; p < 8; p++) {
            int i  = (tid >> 5) + p * 8;
            int d4 = (tid & 31) * 4;
            *(float4*)&Ks[i * FROWSTRIDE + d4] =
                *(const float4*)&K[base + (size_t)(k0 + i) * DIM + d4];
            *(float4*)&Vs[i * FROWSTRIDE + d4] =
                *(const float4*)&V[base + (size_t)(k0 + i) * DIM + d4];
        }
        __syncthreads();

        // Scores: packed pairs along d (both operands contiguous, no dups).
        u64t cs2[4][4] = {};
        #pragma unroll 4
        for (int d0 = 0; d0 < DH; d0 += 4) {
            ulonglong2 q2[4], k2[4];
            #pragma unroll
            for (int r = 0; r < 4; r++)
                q2[r] = *(const ulonglong2*)&Qs[(ty * 4 + r) * FROWSTRIDE + d0];
            #pragma unroll
            for (int s = 0; s < 4; s++)
                k2[s] = *(const ulonglong2*)&Ks[(tx * 4 + s) * FROWSTRIDE + d0];
            #pragma unroll
            for (int r = 0; r < 4; r++)
                #pragma unroll
                for (int s = 0; s < 4; s++) {
                    fma2(cs2[r][s], q2[r].x, k2[s].x);
                    fma2(cs2[r][s], q2[r].y, k2[s].y);
                }
        }

        // Horizontal add + scale + causal mask -> Ps
        #pragma unroll
        for (int r = 0; r < 4; r++) {
            int gq = q0 + ty * 4 + r;
            int gk = k0 + tx * 4;
            float4 o;
            float v0 = (lo32(cs2[r][0]) + hi32(cs2[r][0])) * scale;
            float v1 = (lo32(cs2[r][1]) + hi32(cs2[r][1])) * scale;
            float v2 = (lo32(cs2[r][2]) + hi32(cs2[r][2])) * scale;
            float v3 = (lo32(cs2[r][3]) + hi32(cs2[r][3])) * scale;
            o.x = (causal && (gk + 0) > gq) ? -INFINITY : v0;
            o.y = (causal && (gk + 1) > gq) ? -INFINITY : v1;
            o.z = (causal && (gk + 2) > gq) ? -INFINITY : v2;
            o.w = (causal && (gk + 3) > gq) ? -INFINITY : v3;
            *(float4*)&Ps[(ty * 4 + r) * 64 + tx * 4] = o;
        }
        __syncthreads();

        // Online softmax: 4 threads per row (16 cols each) + shfl reduce.
        {
            const int row = tid >> 2;
            const int qtr = tid & 3;
            float* rowp = &Ps[row * 64 + qtr * 16];
            float m_old = mrow[row];
            float4 vv[4];
            float mx = m_old;
            #pragma unroll
            for (int t = 0; t < 4; t++) {
                vv[t] = *(const float4*)&rowp[t * 4];
                mx = fmaxf(mx, fmaxf(fmaxf(vv[t].x, vv[t].y),
                                     fmaxf(vv[t].z, vv[t].w)));
            }
            mx = fmaxf(mx, __shfl_xor_sync(0xffffffffu, mx, 1));
            mx = fmaxf(mx, __shfl_xor_sync(0xffffffffu, mx, 2));
            float s = 0.f;
            #pragma unroll
            for (int t = 0; t < 4; t++) {
                vv[t].x = __expf(vv[t].x - mx);
                vv[t].y = __expf(vv[t].y - mx);
                vv[t].z = __expf(vv[t].z - mx);
                vv[t].w = __expf(vv[t].w - mx);
                s += vv[t].x + vv[t].y + vv[t].z + vv[t].w;
                *(float4*)&rowp[t * 4] = vv[t];
            }
            s += __shfl_xor_sync(0xffffffffu, s, 1);
            s += __shfl_xor_sync(0xffffffffu, s, 2);
            if (qtr == 0) {
                float corr = __expf(m_old - mx);
                lrow[row] = lrow[row] * corr + s;
                mrow[row] = mx;
                crow[row] = corr;
            }
        }
        __syncthreads();

        // Rescale accumulators, then AV accumulate (packed pairs along d).
        #pragma unroll
        for (int r = 0; r < 4; r++) {
            u64t crd = pack2(crow[ty * 4 + r]);
            #pragma unroll
            for (int j = 0; j < 4; j++) acc2[r][j] = mul2(acc2[r][j], crd);
        }

        #pragma unroll 4
        for (int kk = 0; kk < 64; kk++) {
            float pr[4];
            #pragma unroll
            for (int r = 0; r < 4; r++)
                pr[r] = Ps[(ty * 4 + r) * 64 + kk];
            ulonglong2 va = *(const ulonglong2*)&Vs[kk * FROWSTRIDE + tx * 8];
            ulonglong2 vb = *(const ulonglong2*)&Vs[kk * FROWSTRIDE + tx * 8 + 4];
            u64t vp[4] = {va.x, va.y, vb.x, vb.y};
            #pragma unroll
            for (int r = 0; r < 4; r++) {
                u64t pd = pack2(pr[r]);
                fma2(acc2[r][0], pd, vp[0]);
                fma2(acc2[r][1], pd, vp[1]);
                fma2(acc2[r][2], pd, vp[2]);
                fma2(acc2[r][3], pd, vp[3]);
            }
        }
    }

    #pragma unroll
    for (int r = 0; r < 4; r++) {
        int i = ty * 4 + r;
        float inv = 1.f / lrow[i];
        float4 o0, o1;
        o0.x = lo32(acc2[r][0]) * inv; o0.y = hi32(acc2[r][0]) * inv;
        o0.z = lo32(acc2[r][1]) * inv; o0.w = hi32(acc2[r][1]) * inv;
        o1.x = lo32(acc2[r][2]) * inv; o1.y = hi32(acc2[r][2]) * inv;
        o1.z = lo32(acc2[r][3]) * inv; o1.w = hi32(acc2[r][3]) * inv;
        float* orow = &O[base + (size_t)(q0 + i) * DIM + tx * 8];
        *(float4*)&orow[0] = o0;
        *(float4*)&orow[4] = o1;
    }
}

// ===========================================================================
extern "C" void kernel_launch(void* const* d_in, const int* in_sizes, int n_in,
                              void* d_out, int out_size)
{
    const float* q      = (const float*)d_in[0];
    const float* k      = (const float*)d_in[1];
    const float* v      = (const float*)d_in[2];
    const float* Wq     = (const float*)d_in[3];
    const float* bq     = (const float*)d_in[4];
    const float* Wk     = (const float*)d_in[5];
    const float* bk     = (const float*)d_in[6];
    const float* Wv     = (const float*)d_in[7];
    const float* bv     = (const float*)d_in[8];
    const float* Wo     = (const float*)d_in[9];
    const float* bo     = (const float*)d_in[10];
    const int*   causal = (const int*)d_in[11];
    float* out = (float*)d_out;

    float *Qb, *Kb, *Vb, *Ab;
    cudaGetSymbolAddress((void**)&Qb, g_Q);
    cudaGetSymbolAddress((void**)&Kb, g_K);
    cudaGetSymbolAddress((void**)&Vb, g_V);
    cudaGetSymbolAddress((void**)&Ab, g_A);

    const int M = BATCH * SEQ;                   // 4096
    dim3 ggrid(DIM / 128, M / 128);              // (16, 32)

    cudaFuncSetAttribute(flash_kernel,
                         cudaFuncAttributeMaxDynamicSharedMemorySize,
                         FLASH_SMEM_BYTES);

    gemm_f32x2_kernel<<<ggrid, 256>>>(q, Wq, bq, Qb, M, DIM, DIM);
    gemm_f32x2_kernel<<<ggrid, 256>>>(k, Wk, bk, Kb, M, DIM, DIM);
    gemm_f32x2_kernel<<<ggrid, 256>>>(v, Wv, bv, Vb, M, DIM, DIM);

    dim3 fgrid(SEQ / 64, NH, BATCH);             // (32, 16, 2)
    flash_kernel<<<fgrid, 256, FLASH_SMEM_BYTES>>>(Qb, Kb, Vb, causal, Ab);

    gemm_f32x2_kernel<<<ggrid, 256>>>(Ab, Wo, bo, out, M, DIM, DIM);
}

// round 8
// speedup vs baseline: 1.8588x; 1.5819x over previous
#include <cuda_runtime.h>
#include <cuda_bf16.h>
#include <math.h>
#include <stdint.h>

#define BATCH 2
#define SEQ   2048
#define DIM   2048
#define NH    16
#define DH    128

// Scratch — __device__ globals per allocation rules.
__device__ float g_Q[BATCH * SEQ * DIM];
__device__ float g_K[BATCH * SEQ * DIM];
__device__ float g_V[BATCH * SEQ * DIM];
__device__ float g_A[BATCH * SEQ * DIM];
__device__ __nv_bfloat16 g_Ah[BATCH * SEQ * DIM];
__device__ __nv_bfloat16 g_Al[BATCH * SEQ * DIM];
__device__ __nv_bfloat16 g_Wh[DIM * DIM];
__device__ __nv_bfloat16 g_Wl[DIM * DIM];

// ===========================================================================
// Helpers
// ===========================================================================
typedef unsigned long long u64t;

__device__ __forceinline__ uint32_t smem_u32(const void* p) {
    uint32_t a;
    asm("{ .reg .u64 t; cvta.to.shared.u64 t, %1; cvt.u32.u64 %0, t; }"
        : "=r"(a) : "l"(p));
    return a;
}

__device__ __forceinline__ void fma2(u64t& c, u64t a, u64t b) {
    asm("fma.rn.f32x2 %0, %1, %2, %0;" : "+l"(c) : "l"(a), "l"(b));
}
__device__ __forceinline__ u64t mul2(u64t a, u64t b) {
    u64t r;
    asm("mul.rn.f32x2 %0, %1, %2;" : "=l"(r) : "l"(a), "l"(b));
    return r;
}
__device__ __forceinline__ u64t pack2(float x) {
    u64t r;
    asm("mov.b64 %0, {%1, %2};" : "=l"(r) : "f"(x), "f"(x));
    return r;
}
__device__ __forceinline__ float lo32(u64t v) { return __uint_as_float((unsigned)v); }
__device__ __forceinline__ float hi32(u64t v) { return __uint_as_float((unsigned)(v >> 32)); }

__device__ __forceinline__ void split2(float x, float y, uint32_t& h, uint32_t& l) {
    __nv_bfloat16 hx = __float2bfloat16_rn(x);
    __nv_bfloat16 hy = __float2bfloat16_rn(y);
    float rx = x - __bfloat162float(hx);
    float ry = y - __bfloat162float(hy);
    __nv_bfloat16 lx = __float2bfloat16_rn(rx);
    __nv_bfloat16 ly = __float2bfloat16_rn(ry);
    h = (uint32_t)__bfloat16_as_ushort(hx) | ((uint32_t)__bfloat16_as_ushort(hy) << 16);
    l = (uint32_t)__bfloat16_as_ushort(lx) | ((uint32_t)__bfloat16_as_ushort(ly) << 16);
}

__device__ __forceinline__ void ldsm_x4(uint32_t addr, uint32_t r[4]) {
    asm volatile("ldmatrix.sync.aligned.m8n8.x4.shared.b16 {%0,%1,%2,%3}, [%4];"
                 : "=r"(r[0]), "=r"(r[1]), "=r"(r[2]), "=r"(r[3]) : "r"(addr));
}

__device__ __forceinline__ void mma_bf16(float c[4], const uint32_t a[4],
                                         const uint32_t b0, const uint32_t b1) {
    asm volatile(
        "mma.sync.aligned.m16n8k16.row.col.f32.bf16.bf16.f32 "
        "{%0,%1,%2,%3}, {%4,%5,%6,%7}, {%8,%9}, {%0,%1,%2,%3};"
        : "+f"(c[0]), "+f"(c[1]), "+f"(c[2]), "+f"(c[3])
        : "r"(a[0]), "r"(a[1]), "r"(a[2]), "r"(a[3]), "r"(b0), "r"(b1));
}

__device__ __forceinline__ void cp16(uint32_t saddr, const void* gaddr) {
    asm volatile("cp.async.ca.shared.global [%0], [%1], 16;"
                 :: "r"(saddr), "l"(gaddr));
}
#define CP_COMMIT() asm volatile("cp.async.commit_group;" ::: "memory")
#define CP_WAIT(n)  asm volatile("cp.async.wait_group %0;" :: "n"(n) : "memory")

// ===========================================================================
// Split conversion: fp32 array -> bf16 hi + bf16 lo arrays.
// ===========================================================================
__global__ __launch_bounds__(256) void split_kernel(
    const float* __restrict__ in, __nv_bfloat16* __restrict__ hi,
    __nv_bfloat16* __restrict__ lo, int n4)
{
    int i = blockIdx.x * blockDim.x + threadIdx.x;
    if (i >= n4) return;
    float4 v = ((const float4*)in)[i];
    uint2 h, l;
    split2(v.x, v.y, h.x, l.x);
    split2(v.z, v.w, h.y, l.y);
    ((uint2*)hi)[i] = h;
    ((uint2*)lo)[i] = l;
}

// ===========================================================================
// Pure-bf16 split HMMA GEMM: C = A @ W^T + bias, A=Ah+Al, W=Wh+Wl.
// CTA 128x128, BK=32, 8 warps (2x4) warp tile 64x32, 3-pass accumulation.
// cp.async 3-stage pipeline; RS=40 bf16 rows (80B) -> conflict-free ldmatrix.
// ===========================================================================
#define GRS    40
#define GTILE  (128 * GRS * 2)          // 10240 B per operand tile
#define GSTAGE (4 * GTILE)              // 40960 B per stage (Ah,Al,Wh,Wl)
#define NSTG   3
#define GEMM_SMEM (NSTG * GSTAGE)       // 122880 B

__global__ __launch_bounds__(256, 1) void gemm_bf16_kernel(
    const __nv_bfloat16* __restrict__ Ah, const __nv_bfloat16* __restrict__ Al,
    const __nv_bfloat16* __restrict__ Wh, const __nv_bfloat16* __restrict__ Wl,
    const float* __restrict__ bias, float* __restrict__ C,
    int M, int N, int Kd)
{
    extern __shared__ char smem[];
    const uint32_t sbase = smem_u32(smem);
    const int tid  = threadIdx.x;
    const int wid  = tid >> 5;
    const int lane = tid & 31;
    const int wm   = wid >> 2;
    const int wn   = wid & 3;
    const int bm   = blockIdx.y * 128;
    const int bn   = blockIdx.x * 128;

    float acc[4][4][4];
    #pragma unroll
    for (int i = 0; i < 4; i++)
        #pragma unroll
        for (int j = 0; j < 4; j++)
            #pragma unroll
            for (int e = 0; e < 4; e++) acc[i][j][e] = 0.f;

    // cp.async coords: 512 16B-chunks per tile, 2 per thread.
    const int row0 = tid >> 2;          // 0..63
    const int row1 = row0 + 64;         // 64..127
    const int c4   = tid & 3;           // 16B chunk within 64B row

#define ISSUE_STAGE(CH, STG) do {                                             \
    const int k0_ = (CH) * 32;                                                \
    const uint32_t sb_ = sbase + (STG) * GSTAGE;                              \
    const uint32_t so0 = (uint32_t)(row0 * 80 + c4 * 16);                     \
    const uint32_t so1 = (uint32_t)(row1 * 80 + c4 * 16);                     \
    const size_t ao0 = (size_t)(bm + row0) * Kd + k0_ + c4 * 8;               \
    const size_t ao1 = (size_t)(bm + row1) * Kd + k0_ + c4 * 8;               \
    const size_t wo0 = (size_t)(bn + row0) * Kd + k0_ + c4 * 8;               \
    const size_t wo1 = (size_t)(bn + row1) * Kd + k0_ + c4 * 8;               \
    cp16(sb_ + so0,              Ah + ao0);                                   \
    cp16(sb_ + so1,              Ah + ao1);                                   \
    cp16(sb_ + GTILE + so0,      Al + ao0);                                   \
    cp16(sb_ + GTILE + so1,      Al + ao1);                                   \
    cp16(sb_ + 2 * GTILE + so0,  Wh + wo0);                                   \
    cp16(sb_ + 2 * GTILE + so1,  Wh + wo1);                                   \
    cp16(sb_ + 3 * GTILE + so0,  Wl + wo0);                                   \
    cp16(sb_ + 3 * GTILE + so1,  Wl + wo1);                                   \
} while (0)

    #pragma unroll
    for (int s = 0; s < NSTG; s++) { ISSUE_STAGE(s, s); CP_COMMIT(); }

    const int g  = lane >> 3;
    const int r8 = lane & 7;
    const int nchunk = Kd / 32;         // 64

    for (int ch = 0; ch < nchunk; ch++) {
        CP_WAIT(NSTG - 1);              // oldest group (this stage) done
        __syncthreads();
        const uint32_t buf = sbase + (ch % NSTG) * GSTAGE;

        #pragma unroll
        for (int ks = 0; ks < 2; ks++) {
            const int k0 = ks * 16;
            uint32_t ah[4][4], al[4][4];
            #pragma unroll
            for (int mt = 0; mt < 4; mt++) {
                int row = wm * 64 + mt * 16 + r8 + (g & 1) * 8;
                uint32_t off = (uint32_t)(row * GRS + k0 + (g >> 1) * 8) * 2;
                ldsm_x4(buf + off, ah[mt]);
                ldsm_x4(buf + GTILE + off, al[mt]);
            }
            uint32_t bh[2][4], bl[2][4];
            #pragma unroll
            for (int np = 0; np < 2; np++) {
                int nrow = wn * 32 + np * 16 + r8 + (g >> 1) * 8;
                uint32_t off = (uint32_t)(nrow * GRS + k0 + (g & 1) * 8) * 2;
                ldsm_x4(buf + 2 * GTILE + off, bh[np]);
                ldsm_x4(buf + 3 * GTILE + off, bl[np]);
            }
            #pragma unroll
            for (int mt = 0; mt < 4; mt++) {
                #pragma unroll
                for (int nt = 0; nt < 4; nt++) {
                    const int np = nt >> 1, hf = (nt & 1) * 2;
                    mma_bf16(acc[mt][nt], ah[mt], bh[np][hf], bh[np][hf + 1]);
                    mma_bf16(acc[mt][nt], ah[mt], bl[np][hf], bl[np][hf + 1]);
                    mma_bf16(acc[mt][nt], al[mt], bh[np][hf], bh[np][hf + 1]);
                }
            }
        }
        __syncthreads();
        if (ch + NSTG < nchunk) ISSUE_STAGE(ch + NSTG, ch % NSTG);
        CP_COMMIT();
    }

    // Epilogue (proven mapping from round 4).
    #pragma unroll
    for (int nt = 0; nt < 4; nt++) {
        const int gcol = bn + wn * 32 + nt * 8 + (lane & 3) * 2;
        const float2 bv = *(const float2*)&bias[gcol];
        #pragma unroll
        for (int mt = 0; mt < 4; mt++) {
            const int grow = bm + wm * 64 + mt * 16 + (lane >> 2);
            float2 o0, o1;
            o0.x = acc[mt][nt][0] + bv.x;
            o0.y = acc[mt][nt][1] + bv.y;
            o1.x = acc[mt][nt][2] + bv.x;
            o1.y = acc[mt][nt][3] + bv.y;
            *(float2*)&C[(size_t)grow * N + gcol] = o0;
            *(float2*)&C[(size_t)(grow + 8) * N + gcol] = o1;
        }
    }
#undef ISSUE_STAGE
}

// ===========================================================================
// Flash attention (fp32, causal) — unchanged from round 7.
// ===========================================================================
#define FROWSTRIDE 132
#define FLASH_SMEM_FLOATS (3 * 64 * FROWSTRIDE + 64 * 64 + 3 * 64)
#define FLASH_SMEM_BYTES  (FLASH_SMEM_FLOATS * 4)

__global__ __launch_bounds__(256) void flash_kernel(
    const float* __restrict__ Q, const float* __restrict__ K,
    const float* __restrict__ V, const int* __restrict__ causal_ptr,
    float* __restrict__ O)
{
    extern __shared__ float sm[];
    float* Qs   = sm;
    float* Ks   = Qs + 64 * FROWSTRIDE;
    float* Vs   = Ks + 64 * FROWSTRIDE;
    float* Ps   = Vs + 64 * FROWSTRIDE;
    float* mrow = Ps + 64 * 64;
    float* lrow = mrow + 64;
    float* crow = lrow + 64;

    const int tid = threadIdx.x;
    const int tx  = tid & 15;
    const int ty  = tid >> 4;
    const int qt  = blockIdx.x;
    const int h   = blockIdx.y;
    const int b   = blockIdx.z;
    const int q0  = qt * 64;
    const size_t base = (size_t)b * SEQ * DIM + (size_t)h * DH;
    const int causal = *causal_ptr;
    const float scale = 0.08838834764831845f;

    #pragma unroll
    for (int p = 0; p < 8; p++) {
        int i  = (tid >> 5) + p * 8;
        int d4 = (tid & 31) * 4;
        *(float4*)&Qs[i * FROWSTRIDE + d4] =
            *(const float4*)&Q[base + (size_t)(q0 + i) * DIM + d4];
    }
    if (tid < 64) { mrow[tid] = -INFINITY; lrow[tid] = 0.f; }

    u64t acc2[4][4] = {};

    const int nkt = causal ? (qt + 1) : (SEQ / 64);

    for (int kt = 0; kt < nkt; kt++) {
        const int k0 = kt * 64;
        __syncthreads();

        #pragma unroll
        for (int p = 0; p < 8; p++) {
            int i  = (tid >> 5) + p * 8;
            int d4 = (tid & 31) * 4;
            *(float4*)&Ks[i * FROWSTRIDE + d4] =
                *(const float4*)&K[base + (size_t)(k0 + i) * DIM + d4];
            *(float4*)&Vs[i * FROWSTRIDE + d4] =
                *(const float4*)&V[base + (size_t)(k0 + i) * DIM + d4];
        }
        __syncthreads();

        u64t cs2[4][4] = {};
        #pragma unroll 4
        for (int d0 = 0; d0 < DH; d0 += 4) {
            ulonglong2 q2[4], k2[4];
            #pragma unroll
            for (int r = 0; r < 4; r++)
                q2[r] = *(const ulonglong2*)&Qs[(ty * 4 + r) * FROWSTRIDE + d0];
            #pragma unroll
            for (int s = 0; s < 4; s++)
                k2[s] = *(const ulonglong2*)&Ks[(tx * 4 + s) * FROWSTRIDE + d0];
            #pragma unroll
            for (int r = 0; r < 4; r++)
                #pragma unroll
                for (int s = 0; s < 4; s++) {
                    fma2(cs2[r][s], q2[r].x, k2[s].x);
                    fma2(cs2[r][s], q2[r].y, k2[s].y);
                }
        }

        #pragma unroll
        for (int r = 0; r < 4; r++) {
            int gq = q0 + ty * 4 + r;
            int gk = k0 + tx * 4;
            float4 o;
            float v0 = (lo32(cs2[r][0]) + hi32(cs2[r][0])) * scale;
            float v1 = (lo32(cs2[r][1]) + hi32(cs2[r][1])) * scale;
            float v2 = (lo32(cs2[r][2]) + hi32(cs2[r][2])) * scale;
            float v3 = (lo32(cs2[r][3]) + hi32(cs2[r][3])) * scale;
            o.x = (causal && (gk + 0) > gq) ? -INFINITY : v0;
            o.y = (causal && (gk + 1) > gq) ? -INFINITY : v1;
            o.z = (causal && (gk + 2) > gq) ? -INFINITY : v2;
            o.w = (causal && (gk + 3) > gq) ? -INFINITY : v3;
            *(float4*)&Ps[(ty * 4 + r) * 64 + tx * 4] = o;
        }
        __syncthreads();

        {
            const int row = tid >> 2;
            const int qtr = tid & 3;
            float* rowp = &Ps[row * 64 + qtr * 16];
            float m_old = mrow[row];
            float4 vv[4];
            float mx = m_old;
            #pragma unroll
            for (int t = 0; t < 4; t++) {
                vv[t] = *(const float4*)&rowp[t * 4];
                mx = fmaxf(mx, fmaxf(fmaxf(vv[t].x, vv[t].y),
                                     fmaxf(vv[t].z, vv[t].w)));
            }
            mx = fmaxf(mx, __shfl_xor_sync(0xffffffffu, mx, 1));
            mx = fmaxf(mx, __shfl_xor_sync(0xffffffffu, mx, 2));
            float s = 0.f;
            #pragma unroll
            for (int t = 0; t < 4; t++) {
                vv[t].x = __expf(vv[t].x - mx);
                vv[t].y = __expf(vv[t].y - mx);
                vv[t].z = __expf(vv[t].z - mx);
                vv[t].w = __expf(vv[t].w - mx);
                s += vv[t].x + vv[t].y + vv[t].z + vv[t].w;
                *(float4*)&rowp[t * 4] = vv[t];
            }
            s += __shfl_xor_sync(0xffffffffu, s, 1);
            s += __shfl_xor_sync(0xffffffffu, s, 2);
            if (qtr == 0) {
                float corr = __expf(m_old - mx);
                lrow[row] = lrow[row] * corr + s;
                mrow[row] = mx;
                crow[row] = corr;
            }
        }
        __syncthreads();

        #pragma unroll
        for (int r = 0; r < 4; r++) {
            u64t crd = pack2(crow[ty * 4 + r]);
            #pragma unroll
            for (int j = 0; j < 4; j++) acc2[r][j] = mul2(acc2[r][j], crd);
        }

        #pragma unroll 4
        for (int kk = 0; kk < 64; kk++) {
            float pr[4];
            #pragma unroll
            for (int r = 0; r < 4; r++)
                pr[r] = Ps[(ty * 4 + r) * 64 + kk];
            ulonglong2 va = *(const ulonglong2*)&Vs[kk * FROWSTRIDE + tx * 8];
            ulonglong2 vb = *(const ulonglong2*)&Vs[kk * FROWSTRIDE + tx * 8 + 4];
            u64t vp[4] = {va.x, va.y, vb.x, vb.y};
            #pragma unroll
            for (int r = 0; r < 4; r++) {
                u64t pd = pack2(pr[r]);
                fma2(acc2[r][0], pd, vp[0]);
                fma2(acc2[r][1], pd, vp[1]);
                fma2(acc2[r][2], pd, vp[2]);
                fma2(acc2[r][3], pd, vp[3]);
            }
        }
    }

    #pragma unroll
    for (int r = 0; r < 4; r++) {
        int i = ty * 4 + r;
        float inv = 1.f / lrow[i];
        float4 o0, o1;
        o0.x = lo32(acc2[r][0]) * inv; o0.y = hi32(acc2[r][0]) * inv;
        o0.z = lo32(acc2[r][1]) * inv; o0.w = hi32(acc2[r][1]) * inv;
        o1.x = lo32(acc2[r][2]) * inv; o1.y = hi32(acc2[r][2]) * inv;
        o1.z = lo32(acc2[r][3]) * inv; o1.w = hi32(acc2[r][3]) * inv;
        float* orow = &O[base + (size_t)(q0 + i) * DIM + tx * 8];
        *(float4*)&orow[0] = o0;
        *(float4*)&orow[4] = o1;
    }
}

// ===========================================================================
extern "C" void kernel_launch(void* const* d_in, const int* in_sizes, int n_in,
                              void* d_out, int out_size)
{
    const float* q      = (const float*)d_in[0];
    const float* k      = (const float*)d_in[1];
    const float* v      = (const float*)d_in[2];
    const float* Wq     = (const float*)d_in[3];
    const float* bq     = (const float*)d_in[4];
    const float* Wk     = (const float*)d_in[5];
    const float* bk     = (const float*)d_in[6];
    const float* Wv     = (const float*)d_in[7];
    const float* bv     = (const float*)d_in[8];
    const float* Wo     = (const float*)d_in[9];
    const float* bo     = (const float*)d_in[10];
    const int*   causal = (const int*)d_in[11];
    float* out = (float*)d_out;

    float *Qb, *Kb, *Vb, *Ab;
    __nv_bfloat16 *Ahp, *Alp, *Whp, *Wlp;
    cudaGetSymbolAddress((void**)&Qb, g_Q);
    cudaGetSymbolAddress((void**)&Kb, g_K);
    cudaGetSymbolAddress((void**)&Vb, g_V);
    cudaGetSymbolAddress((void**)&Ab, g_A);
    cudaGetSymbolAddress((void**)&Ahp, g_Ah);
    cudaGetSymbolAddress((void**)&Alp, g_Al);
    cudaGetSymbolAddress((void**)&Whp, g_Wh);
    cudaGetSymbolAddress((void**)&Wlp, g_Wl);

    const int M = BATCH * SEQ;                   // 4096
    const int n4x = M * DIM / 4;                 // 2097152
    const int n4w = DIM * DIM / 4;               // 1048576
    dim3 ggrid(DIM / 128, M / 128);              // (16, 32)

    cudaFuncSetAttribute(gemm_bf16_kernel,
                         cudaFuncAttributeMaxDynamicSharedMemorySize, GEMM_SMEM);
    cudaFuncSetAttribute(flash_kernel,
                         cudaFuncAttributeMaxDynamicSharedMemorySize, FLASH_SMEM_BYTES);

    // Q projection
    split_kernel<<<n4x / 256, 256>>>(q, Ahp, Alp, n4x);
    split_kernel<<<n4w / 256, 256>>>(Wq, Whp, Wlp, n4w);
    gemm_bf16_kernel<<<ggrid, 256, GEMM_SMEM>>>(Ahp, Alp, Whp, Wlp, bq, Qb, M, DIM, DIM);
    // K projection
    split_kernel<<<n4x / 256, 256>>>(k, Ahp, Alp, n4x);
    split_kernel<<<n4w / 256, 256>>>(Wk, Whp, Wlp, n4w);
    gemm_bf16_kernel<<<ggrid, 256, GEMM_SMEM>>>(Ahp, Alp, Whp, Wlp, bk, Kb, M, DIM, DIM);
    // V projection
    split_kernel<<<n4x / 256, 256>>>(v, Ahp, Alp, n4x);
    split_kernel<<<n4w / 256, 256>>>(Wv, Whp, Wlp, n4w);
    gemm_bf16_kernel<<<ggrid, 256, GEMM_SMEM>>>(Ahp, Alp, Whp, Wlp, bv, Vb, M, DIM, DIM);

    // Attention
    dim3 fgrid(SEQ / 64, NH, BATCH);             // (32, 16, 2)
    flash_kernel<<<fgrid, 256, FLASH_SMEM_BYTES>>>(Qb, Kb, Vb, causal, Ab);

    // Output projection
    split_kernel<<<n4x / 256, 256>>>(Ab, Ahp, Alp, n4x);
    split_kernel<<<n4w / 256, 256>>>(Wo, Whp, Wlp, n4w);
    gemm_bf16_kernel<<<ggrid, 256, GEMM_SMEM>>>(Ahp, Alp, Whp, Wlp, bo, out, M, DIM, DIM);
}

// round 9
// speedup vs baseline: 2.4920x; 1.3406x over previous
#include <cuda_runtime.h>
#include <cuda_fp16.h>
#include <math.h>
#include <stdint.h>

#define BATCH 2
#define SEQ   2048
#define DIM   2048
#define NH    16
#define DH    128

// Scratch — __device__ globals per allocation rules.
__device__ float g_Q[BATCH * SEQ * DIM];
__device__ float g_K[BATCH * SEQ * DIM];
__device__ float g_V[BATCH * SEQ * DIM];
__device__ float g_A[BATCH * SEQ * DIM];
__device__ __half g_hA[BATCH * SEQ * DIM];   // fp16 activation buffer
__device__ __half g_hW[DIM * DIM];           // fp16 weight buffer

// ===========================================================================
// Helpers
// ===========================================================================
typedef unsigned long long u64t;

__device__ __forceinline__ uint32_t smem_u32(const void* p) {
    uint32_t a;
    asm("{ .reg .u64 t; cvta.to.shared.u64 t, %1; cvt.u32.u64 %0, t; }"
        : "=r"(a) : "l"(p));
    return a;
}

__device__ __forceinline__ void fma2(u64t& c, u64t a, u64t b) {
    asm("fma.rn.f32x2 %0, %1, %2, %0;" : "+l"(c) : "l"(a), "l"(b));
}
__device__ __forceinline__ u64t mul2(u64t a, u64t b) {
    u64t r;
    asm("mul.rn.f32x2 %0, %1, %2;" : "=l"(r) : "l"(a), "l"(b));
    return r;
}
__device__ __forceinline__ u64t pack2(float x) {
    u64t r;
    asm("mov.b64 %0, {%1, %2};" : "=l"(r) : "f"(x), "f"(x));
    return r;
}
__device__ __forceinline__ float lo32(u64t v) { return __uint_as_float((unsigned)v); }
__device__ __forceinline__ float hi32(u64t v) { return __uint_as_float((unsigned)(v >> 32)); }

__device__ __forceinline__ void ldsm_x4(uint32_t addr, uint32_t r[4]) {
    asm volatile("ldmatrix.sync.aligned.m8n8.x4.shared.b16 {%0,%1,%2,%3}, [%4];"
                 : "=r"(r[0]), "=r"(r[1]), "=r"(r[2]), "=r"(r[3]) : "r"(addr));
}

__device__ __forceinline__ void mma_f16(float c[4], const uint32_t a[4],
                                        const uint32_t b0, const uint32_t b1) {
    asm volatile(
        "mma.sync.aligned.m16n8k16.row.col.f32.f16.f16.f32 "
        "{%0,%1,%2,%3}, {%4,%5,%6,%7}, {%8,%9}, {%0,%1,%2,%3};"
        : "+f"(c[0]), "+f"(c[1]), "+f"(c[2]), "+f"(c[3])
        : "r"(a[0]), "r"(a[1]), "r"(a[2]), "r"(a[3]), "r"(b0), "r"(b1));
}

__device__ __forceinline__ void cp16(uint32_t saddr, const void* gaddr) {
    asm volatile("cp.async.ca.shared.global [%0], [%1], 16;"
                 :: "r"(saddr), "l"(gaddr));
}
#define CP_COMMIT() asm volatile("cp.async.commit_group;" ::: "memory")
#define CP_WAIT(n)  asm volatile("cp.async.wait_group %0;" :: "n"(n) : "memory")

// ===========================================================================
// Conversion: fp32 -> fp16 (rn)
// ===========================================================================
__global__ __launch_bounds__(256) void cvt_kernel(
    const float* __restrict__ in, __half* __restrict__ out, int n4)
{
    int i = blockIdx.x * blockDim.x + threadIdx.x;
    if (i >= n4) return;
    float4 v = ((const float4*)in)[i];
    __half2 h0 = __floats2half2_rn(v.x, v.y);
    __half2 h1 = __floats2half2_rn(v.z, v.w);
    uint2 o;
    o.x = *(uint32_t*)&h0;
    o.y = *(uint32_t*)&h1;
    ((uint2*)out)[i] = o;
}

// ===========================================================================
// fp16 single-pass HMMA GEMM: C[M,N] = A[M,K] @ W[N,K]^T + bias (fp32 out)
// CTA 128x128, BK=32, 8 warps (2x4) warp tile 64x32.
// cp.async 3-stage pipeline; RS=40 fp16 rows (80B) -> conflict-free ldmatrix.
// ===========================================================================
#define GRS    40
#define GTILE  (128 * GRS * 2)          // 10240 B per operand tile
#define GSTAGE (2 * GTILE)              // 20480 B per stage (A, W)
#define NSTG   3
#define GEMM_SMEM (NSTG * GSTAGE)       // 61440 B

__global__ __launch_bounds__(256, 2) void gemm_f16_kernel(
    const __half* __restrict__ Ah, const __half* __restrict__ Wh,
    const float* __restrict__ bias, float* __restrict__ C,
    int M, int N, int Kd)
{
    extern __shared__ char smem[];
    const uint32_t sbase = smem_u32(smem);
    const int tid  = threadIdx.x;
    const int wid  = tid >> 5;
    const int lane = tid & 31;
    const int wm   = wid >> 2;
    const int wn   = wid & 3;
    const int bm   = blockIdx.y * 128;
    const int bn   = blockIdx.x * 128;

    float acc[4][4][4];
    #pragma unroll
    for (int i = 0; i < 4; i++)
        #pragma unroll
        for (int j = 0; j < 4; j++)
            #pragma unroll
            for (int e = 0; e < 4; e++) acc[i][j][e] = 0.f;

    // cp.async coords: tile = 128 rows x 64B (4 chunks of 16B). 512 chunks,
    // 2 per thread per tile.
    const int c0r = tid >> 2, c0c = tid & 3;              // chunk tid
    const int c1r = (tid + 256) >> 2, c1c = tid & 3;      // chunk tid+256

#define ISSUE_STAGE(CH, STG) do {                                             \
    const int k0_ = (CH) * 32;                                                \
    const uint32_t sb_ = sbase + (STG) * GSTAGE;                              \
    const uint32_t so0 = (uint32_t)(c0r * 80 + c0c * 16);                     \
    const uint32_t so1 = (uint32_t)(c1r * 80 + c1c * 16);                     \
    cp16(sb_ + so0,         Ah + (size_t)(bm + c0r) * Kd + k0_ + c0c * 8);    \
    cp16(sb_ + so1,         Ah + (size_t)(bm + c1r) * Kd + k0_ + c1c * 8);    \
    cp16(sb_ + GTILE + so0, Wh + (size_t)(bn + c0r) * Kd + k0_ + c0c * 8);    \
    cp16(sb_ + GTILE + so1, Wh + (size_t)(bn + c1r) * Kd + k0_ + c1c * 8);    \
} while (0)

    #pragma unroll
    for (int s = 0; s < NSTG; s++) { ISSUE_STAGE(s, s); CP_COMMIT(); }

    const int g  = lane >> 3;
    const int r8 = lane & 7;
    const int nchunk = Kd / 32;         // 64

    for (int ch = 0; ch < nchunk; ch++) {
        CP_WAIT(NSTG - 1);
        __syncthreads();
        const uint32_t buf = sbase + (ch % NSTG) * GSTAGE;

        #pragma unroll
        for (int ks = 0; ks < 2; ks++) {
            const int k0 = ks * 16;
            uint32_t af[4][4];
            #pragma unroll
            for (int mt = 0; mt < 4; mt++) {
                int row = wm * 64 + mt * 16 + r8 + (g & 1) * 8;
                uint32_t off = (uint32_t)(row * GRS + k0 + (g >> 1) * 8) * 2;
                ldsm_x4(buf + off, af[mt]);
            }
            uint32_t bf[2][4];
            #pragma unroll
            for (int np = 0; np < 2; np++) {
                int nrow = wn * 32 + np * 16 + r8 + (g >> 1) * 8;
                uint32_t off = (uint32_t)(nrow * GRS + k0 + (g & 1) * 8) * 2;
                ldsm_x4(buf + GTILE + off, bf[np]);
            }
            #pragma unroll
            for (int mt = 0; mt < 4; mt++) {
                #pragma unroll
                for (int nt = 0; nt < 4; nt++) {
                    const int np = nt >> 1, hf = (nt & 1) * 2;
                    mma_f16(acc[mt][nt], af[mt], bf[np][hf], bf[np][hf + 1]);
                }
            }
        }
        __syncthreads();
        if (ch + NSTG < nchunk) ISSUE_STAGE(ch + NSTG, ch % NSTG);
        CP_COMMIT();
    }

    // Epilogue (proven mapping).
    #pragma unroll
    for (int nt = 0; nt < 4; nt++) {
        const int gcol = bn + wn * 32 + nt * 8 + (lane & 3) * 2;
        const float2 bv = *(const float2*)&bias[gcol];
        #pragma unroll
        for (int mt = 0; mt < 4; mt++) {
            const int grow = bm + wm * 64 + mt * 16 + (lane >> 2);
            float2 o0, o1;
            o0.x = acc[mt][nt][0] + bv.x;
            o0.y = acc[mt][nt][1] + bv.y;
            o1.x = acc[mt][nt][2] + bv.x;
            o1.y = acc[mt][nt][3] + bv.y;
            *(float2*)&C[(size_t)grow * N + gcol] = o0;
            *(float2*)&C[(size_t)(grow + 8) * N + gcol] = o1;
        }
    }
#undef ISSUE_STAGE
}

// ===========================================================================
// Flash attention (fp32, causal) — unchanged (proven).
// ===========================================================================
#define FROWSTRIDE 132
#define FLASH_SMEM_FLOATS (3 * 64 * FROWSTRIDE + 64 * 64 + 3 * 64)
#define FLASH_SMEM_BYTES  (FLASH_SMEM_FLOATS * 4)

__global__ __launch_bounds__(256) void flash_kernel(
    const float* __restrict__ Q, const float* __restrict__ K,
    const float* __restrict__ V, const int* __restrict__ causal_ptr,
    float* __restrict__ O)
{
    extern __shared__ float sm[];
    float* Qs   = sm;
    float* Ks   = Qs + 64 * FROWSTRIDE;
    float* Vs   = Ks + 64 * FROWSTRIDE;
    float* Ps   = Vs + 64 * FROWSTRIDE;
    float* mrow = Ps + 64 * 64;
    float* lrow = mrow + 64;
    float* crow = lrow + 64;

    const int tid = threadIdx.x;
    const int tx  = tid & 15;
    const int ty  = tid >> 4;
    const int qt  = blockIdx.x;
    const int h   = blockIdx.y;
    const int b   = blockIdx.z;
    const int q0  = qt * 64;
    const size_t base = (size_t)b * SEQ * DIM + (size_t)h * DH;
    const int causal = *causal_ptr;
    const float scale = 0.08838834764831845f;

    #pragma unroll
    for (int p = 0; p < 8; p++) {
        int i  = (tid >> 5) + p * 8;
        int d4 = (tid & 31) * 4;
        *(float4*)&Qs[i * FROWSTRIDE + d4] =
            *(const float4*)&Q[base + (size_t)(q0 + i) * DIM + d4];
    }
    if (tid < 64) { mrow[tid] = -INFINITY; lrow[tid] = 0.f; }

    u64t acc2[4][4] = {};

    const int nkt = causal ? (qt + 1) : (SEQ / 64);

    for (int kt = 0; kt < nkt; kt++) {
        const int k0 = kt * 64;
        __syncthreads();

        #pragma unroll
        for (int p = 0; p < 8; p++) {
            int i  = (tid >> 5) + p * 8;
            int d4 = (tid & 31) * 4;
            *(float4*)&Ks[i * FROWSTRIDE + d4] =
                *(const float4*)&K[base + (size_t)(k0 + i) * DIM + d4];
            *(float4*)&Vs[i * FROWSTRIDE + d4] =
                *(const float4*)&V[base + (size_t)(k0 + i) * DIM + d4];
        }
        __syncthreads();

        u64t cs2[4][4] = {};
        #pragma unroll 4
        for (int d0 = 0; d0 < DH; d0 += 4) {
            ulonglong2 q2[4], k2[4];
            #pragma unroll
            for (int r = 0; r < 4; r++)
                q2[r] = *(const ulonglong2*)&Qs[(ty * 4 + r) * FROWSTRIDE + d0];
            #pragma unroll
            for (int s = 0; s < 4; s++)
                k2[s] = *(const ulonglong2*)&Ks[(tx * 4 + s) * FROWSTRIDE + d0];
            #pragma unroll
            for (int r = 0; r < 4; r++)
                #pragma unroll
                for (int s = 0; s < 4; s++) {
                    fma2(cs2[r][s], q2[r].x, k2[s].x);
                    fma2(cs2[r][s], q2[r].y, k2[s].y);
                }
        }

        #pragma unroll
        for (int r = 0; r < 4; r++) {
            int gq = q0 + ty * 4 + r;
            int gk = k0 + tx * 4;
            float4 o;
            float v0 = (lo32(cs2[r][0]) + hi32(cs2[r][0])) * scale;
            float v1 = (lo32(cs2[r][1]) + hi32(cs2[r][1])) * scale;
            float v2 = (lo32(cs2[r][2]) + hi32(cs2[r][2])) * scale;
            float v3 = (lo32(cs2[r][3]) + hi32(cs2[r][3])) * scale;
            o.x = (causal && (gk + 0) > gq) ? -INFINITY : v0;
            o.y = (causal && (gk + 1) > gq) ? -INFINITY : v1;
            o.z = (causal && (gk + 2) > gq) ? -INFINITY : v2;
            o.w = (causal && (gk + 3) > gq) ? -INFINITY : v3;
            *(float4*)&Ps[(ty * 4 + r) * 64 + tx * 4] = o;
        }
        __syncthreads();

        {
            const int row = tid >> 2;
            const int qtr = tid & 3;
            float* rowp = &Ps[row * 64 + qtr * 16];
            float m_old = mrow[row];
            float4 vv[4];
            float mx = m_old;
            #pragma unroll
            for (int t = 0; t < 4; t++) {
                vv[t] = *(const float4*)&rowp[t * 4];
                mx = fmaxf(mx, fmaxf(fmaxf(vv[t].x, vv[t].y),
                                     fmaxf(vv[t].z, vv[t].w)));
            }
            mx = fmaxf(mx, __shfl_xor_sync(0xffffffffu, mx, 1));
            mx = fmaxf(mx, __shfl_xor_sync(0xffffffffu, mx, 2));
            float s = 0.f;
            #pragma unroll
            for (int t = 0; t < 4; t++) {
                vv[t].x = __expf(vv[t].x - mx);
                vv[t].y = __expf(vv[t].y - mx);
                vv[t].z = __expf(vv[t].z - mx);
                vv[t].w = __expf(vv[t].w - mx);
                s += vv[t].x + vv[t].y + vv[t].z + vv[t].w;
                *(float4*)&rowp[t * 4] = vv[t];
            }
            s += __shfl_xor_sync(0xffffffffu, s, 1);
            s += __shfl_xor_sync(0xffffffffu, s, 2);
            if (qtr == 0) {
                float corr = __expf(m_old - mx);
                lrow[row] = lrow[row] * corr + s;
                mrow[row] = mx;
                crow[row] = corr;
            }
        }
        __syncthreads();

        #pragma unroll
        for (int r = 0; r < 4; r++) {
            u64t crd = pack2(crow[ty * 4 + r]);
            #pragma unroll
            for (int j = 0; j < 4; j++) acc2[r][j] = mul2(acc2[r][j], crd);
        }

        #pragma unroll 4
        for (int kk = 0; kk < 64; kk++) {
            float pr[4];
            #pragma unroll
            for (int r = 0; r < 4; r++)
                pr[r] = Ps[(ty * 4 + r) * 64 + kk];
            ulonglong2 va = *(const ulonglong2*)&Vs[kk * FROWSTRIDE + tx * 8];
            ulonglong2 vb = *(const ulonglong2*)&Vs[kk * FROWSTRIDE + tx * 8 + 4];
            u64t vp[4] = {va.x, va.y, vb.x, vb.y};
            #pragma unroll
            for (int r = 0; r < 4; r++) {
                u64t pd = pack2(pr[r]);
                fma2(acc2[r][0], pd, vp[0]);
                fma2(acc2[r][1], pd, vp[1]);
                fma2(acc2[r][2], pd, vp[2]);
                fma2(acc2[r][3], pd, vp[3]);
            }
        }
    }

    #pragma unroll
    for (int r = 0; r < 4; r++) {
        int i = ty * 4 + r;
        float inv = 1.f / lrow[i];
        float4 o0, o1;
        o0.x = lo32(acc2[r][0]) * inv; o0.y = hi32(acc2[r][0]) * inv;
        o0.z = lo32(acc2[r][1]) * inv; o0.w = hi32(acc2[r][1]) * inv;
        o1.x = lo32(acc2[r][2]) * inv; o1.y = hi32(acc2[r][2]) * inv;
        o1.z = lo32(acc2[r][3]) * inv; o1.w = hi32(acc2[r][3]) * inv;
        float* orow = &O[base + (size_t)(q0 + i) * DIM + tx * 8];
        *(float4*)&orow[0] = o0;
        *(float4*)&orow[4] = o1;
    }
}

// ===========================================================================
extern "C" void kernel_launch(void* const* d_in, const int* in_sizes, int n_in,
                              void* d_out, int out_size)
{
    const float* q      = (const float*)d_in[0];
    const float* k      = (const float*)d_in[1];
    const float* v      = (const float*)d_in[2];
    const float* Wq     = (const float*)d_in[3];
    const float* bq     = (const float*)d_in[4];
    const float* Wk     = (const float*)d_in[5];
    const float* bk     = (const float*)d_in[6];
    const float* Wv     = (const float*)d_in[7];
    const float* bv     = (const float*)d_in[8];
    const float* Wo     = (const float*)d_in[9];
    const float* bo     = (const float*)d_in[10];
    const int*   causal = (const int*)d_in[11];
    float* out = (float*)d_out;

    float *Qb, *Kb, *Vb, *Ab;
    __half *hA, *hW;
    cudaGetSymbolAddress((void**)&Qb, g_Q);
    cudaGetSymbolAddress((void**)&Kb, g_K);
    cudaGetSymbolAddress((void**)&Vb, g_V);
    cudaGetSymbolAddress((void**)&Ab, g_A);
    cudaGetSymbolAddress((void**)&hA, g_hA);
    cudaGetSymbolAddress((void**)&hW, g_hW);

    const int M = BATCH * SEQ;                   // 4096
    const int n4x = M * DIM / 4;
    const int n4w = DIM * DIM / 4;
    dim3 ggrid(DIM / 128, M / 128);              // (16, 32)

    cudaFuncSetAttribute(gemm_f16_kernel,
                         cudaFuncAttributeMaxDynamicSharedMemorySize, GEMM_SMEM);
    cudaFuncSetAttribute(flash_kernel,
                         cudaFuncAttributeMaxDynamicSharedMemorySize, FLASH_SMEM_BYTES);

    // Q projection
    cvt_kernel<<<n4x / 256, 256>>>(q, hA, n4x);
    cvt_kernel<<<n4w / 256, 256>>>(Wq, hW, n4w);
    gemm_f16_kernel<<<ggrid, 256, GEMM_SMEM>>>(hA, hW, bq, Qb, M, DIM, DIM);
    // K projection
    cvt_kernel<<<n4x / 256, 256>>>(k, hA, n4x);
    cvt_kernel<<<n4w / 256, 256>>>(Wk, hW, n4w);
    gemm_f16_kernel<<<ggrid, 256, GEMM_SMEM>>>(hA, hW, bk, Kb, M, DIM, DIM);
    // V projection
    cvt_kernel<<<n4x / 256, 256>>>(v, hA, n4x);
    cvt_kernel<<<n4w / 256, 256>>>(Wv, hW, n4w);
    gemm_f16_kernel<<<ggrid, 256, GEMM_SMEM>>>(hA, hW, bv, Vb, M, DIM, DIM);

    // Attention (fp32, unchanged)
    dim3 fgrid(SEQ / 64, NH, BATCH);             // (32, 16, 2)
    flash_kernel<<<fgrid, 256, FLASH_SMEM_BYTES>>>(Qb, Kb, Vb, causal, Ab);

    // Output projection
    cvt_kernel<<<n4x / 256, 256>>>(Ab, hA, n4x);
    cvt_kernel<<<n4w / 256, 256>>>(Wo, hW, n4w);
    gemm_f16_kernel<<<ggrid, 256, GEMM_SMEM>>>(hA, hW, bo, out, M, DIM, DIM);
}

// round 11
// speedup vs baseline: 9.5150x; 3.8182x over previous
#include <cuda_runtime.h>
#include <cuda_fp16.h>
#include <math.h>
#include <stdint.h>

#define BATCH 2
#define SEQ   2048
#define DIM   2048
#define NH    16
#define DH    128

// Scratch — __device__ globals per allocation rules.
__device__ __half g_hQ[BATCH * SEQ * DIM];
__device__ __half g_hK[BATCH * SEQ * DIM];
__device__ __half g_hV[BATCH * SEQ * DIM];
__device__ __half g_hA[BATCH * SEQ * DIM];   // A-side input / attention out
__device__ __half g_hW[DIM * DIM];           // weight buffer

// ===========================================================================
// Helpers
// ===========================================================================
__device__ __forceinline__ uint32_t smem_u32(const void* p) {
    uint32_t a;
    asm("{ .reg .u64 t; cvta.to.shared.u64 t, %1; cvt.u32.u64 %0, t; }"
        : "=r"(a) : "l"(p));
    return a;
}

__device__ __forceinline__ void ldsm_x4(uint32_t addr, uint32_t r[4]) {
    asm volatile("ldmatrix.sync.aligned.m8n8.x4.shared.b16 {%0,%1,%2,%3}, [%4];"
                 : "=r"(r[0]), "=r"(r[1]), "=r"(r[2]), "=r"(r[3]) : "r"(addr));
}
__device__ __forceinline__ void ldsm_x4_t(uint32_t addr, uint32_t r[4]) {
    asm volatile("ldmatrix.sync.aligned.m8n8.x4.trans.shared.b16 {%0,%1,%2,%3}, [%4];"
                 : "=r"(r[0]), "=r"(r[1]), "=r"(r[2]), "=r"(r[3]) : "r"(addr));
}

__device__ __forceinline__ void mma_f16(float c[4], const uint32_t a[4],
                                        const uint32_t b0, const uint32_t b1) {
    asm volatile(
        "mma.sync.aligned.m16n8k16.row.col.f32.f16.f16.f32 "
        "{%0,%1,%2,%3}, {%4,%5,%6,%7}, {%8,%9}, {%0,%1,%2,%3};"
        : "+f"(c[0]), "+f"(c[1]), "+f"(c[2]), "+f"(c[3])
        : "r"(a[0]), "r"(a[1]), "r"(a[2]), "r"(a[3]), "r"(b0), "r"(b1));
}

__device__ __forceinline__ void cp16(uint32_t saddr, const void* gaddr) {
    asm volatile("cp.async.ca.shared.global [%0], [%1], 16;"
                 :: "r"(saddr), "l"(gaddr));
}
#define CP_COMMIT() asm volatile("cp.async.commit_group;" ::: "memory")
#define CP_WAIT(n)  asm volatile("cp.async.wait_group %0;" :: "n"(n) : "memory")

__device__ __forceinline__ uint32_t h2pack(float a, float b) {
    __half2 h = __floats2half2_rn(a, b);
    return *(uint32_t*)&h;
}

// ===========================================================================
// Conversion: fp32 -> fp16 (rn)
// ===========================================================================
__global__ __launch_bounds__(256) void cvt_kernel(
    const float* __restrict__ in, __half* __restrict__ out, int n4)
{
    int i = blockIdx.x * blockDim.x + threadIdx.x;
    if (i >= n4) return;
    float4 v = ((const float4*)in)[i];
    uint2 o;
    o.x = h2pack(v.x, v.y);
    o.y = h2pack(v.z, v.w);
    ((uint2*)out)[i] = o;
}

// ===========================================================================
// fp16 HMMA GEMM: C[M,N] = A[M,K] @ W[N,K]^T + bias
// Output fp32 (Cf) or fp16 (Ch) per outhalf flag.
// ===========================================================================
#define GRS    40
#define GTILE  (128 * GRS * 2)
#define GSTAGE (2 * GTILE)
#define NSTG   3
#define GEMM_SMEM (NSTG * GSTAGE)       // 61440 B

__global__ __launch_bounds__(256, 2) void gemm_f16_kernel(
    const __half* __restrict__ Ah, const __half* __restrict__ Wh,
    const float* __restrict__ bias, float* __restrict__ Cf,
    __half* __restrict__ Ch, int outhalf, int M, int N, int Kd)
{
    extern __shared__ char smem[];
    const uint32_t sbase = smem_u32(smem);
    const int tid  = threadIdx.x;
    const int wid  = tid >> 5;
    const int lane = tid & 31;
    const int wm   = wid >> 2;
    const int wn   = wid & 3;
    const int bm   = blockIdx.y * 128;
    const int bn   = blockIdx.x * 128;

    float acc[4][4][4];
    #pragma unroll
    for (int i = 0; i < 4; i++)
        #pragma unroll
        for (int j = 0; j < 4; j++)
            #pragma unroll
            for (int e = 0; e < 4; e++) acc[i][j][e] = 0.f;

    const int c0r = tid >> 2, c0c = tid & 3;
    const int c1r = (tid + 256) >> 2, c1c = tid & 3;

#define ISSUE_STAGE(CH, STG) do {                                             \
    const int k0_ = (CH) * 32;                                                \
    const uint32_t sb_ = sbase + (STG) * GSTAGE;                              \
    const uint32_t so0 = (uint32_t)(c0r * 80 + c0c * 16);                     \
    const uint32_t so1 = (uint32_t)(c1r * 80 + c1c * 16);                     \
    cp16(sb_ + so0,         Ah + (size_t)(bm + c0r) * Kd + k0_ + c0c * 8);    \
    cp16(sb_ + so1,         Ah + (size_t)(bm + c1r) * Kd + k0_ + c1c * 8);    \
    cp16(sb_ + GTILE + so0, Wh + (size_t)(bn + c0r) * Kd + k0_ + c0c * 8);    \
    cp16(sb_ + GTILE + so1, Wh + (size_t)(bn + c1r) * Kd + k0_ + c1c * 8);    \
} while (0)

    #pragma unroll
    for (int s = 0; s < NSTG; s++) { ISSUE_STAGE(s, s); CP_COMMIT(); }

    const int g  = lane >> 3;
    const int r8 = lane & 7;
    const int nchunk = Kd / 32;

    for (int ch = 0; ch < nchunk; ch++) {
        CP_WAIT(NSTG - 1);
        __syncthreads();
        const uint32_t buf = sbase + (ch % NSTG) * GSTAGE;

        #pragma unroll
        for (int ks = 0; ks < 2; ks++) {
            const int k0 = ks * 16;
            uint32_t af[4][4];
            #pragma unroll
            for (int mt = 0; mt < 4; mt++) {
                int row = wm * 64 + mt * 16 + r8 + (g & 1) * 8;
                uint32_t off = (uint32_t)(row * GRS + k0 + (g >> 1) * 8) * 2;
                ldsm_x4(buf + off, af[mt]);
            }
            uint32_t bf[2][4];
            #pragma unroll
            for (int np = 0; np < 2; np++) {
                int nrow = wn * 32 + np * 16 + r8 + (g >> 1) * 8;
                uint32_t off = (uint32_t)(nrow * GRS + k0 + (g & 1) * 8) * 2;
                ldsm_x4(buf + GTILE + off, bf[np]);
            }
            #pragma unroll
            for (int mt = 0; mt < 4; mt++) {
                #pragma unroll
                for (int nt = 0; nt < 4; nt++) {
                    const int np = nt >> 1, hf = (nt & 1) * 2;
                    mma_f16(acc[mt][nt], af[mt], bf[np][hf], bf[np][hf + 1]);
                }
            }
        }
        __syncthreads();
        if (ch + NSTG < nchunk) ISSUE_STAGE(ch + NSTG, ch % NSTG);
        CP_COMMIT();
    }

    #pragma unroll
    for (int nt = 0; nt < 4; nt++) {
        const int gcol = bn + wn * 32 + nt * 8 + (lane & 3) * 2;
        const float2 bv = *(const float2*)&bias[gcol];
        #pragma unroll
        for (int mt = 0; mt < 4; mt++) {
            const int grow = bm + wm * 64 + mt * 16 + (lane >> 2);
            float x0 = acc[mt][nt][0] + bv.x;
            float y0 = acc[mt][nt][1] + bv.y;
            float x1 = acc[mt][nt][2] + bv.x;
            float y1 = acc[mt][nt][3] + bv.y;
            if (outhalf) {
                *(uint32_t*)&Ch[(size_t)grow * N + gcol] = h2pack(x0, y0);
                *(uint32_t*)&Ch[(size_t)(grow + 8) * N + gcol] = h2pack(x1, y1);
            } else {
                float2 o0 = {x0, y0}, o1 = {x1, y1};
                *(float2*)&Cf[(size_t)grow * N + gcol] = o0;
                *(float2*)&Cf[(size_t)(grow + 8) * N + gcol] = o1;
            }
        }
    }
#undef ISSUE_STAGE
}

// ===========================================================================
// Flash attention, fp16 HMMA, P-in-registers.
// CTA = (b, h, 64-row q tile), 4 warps x 16 q-rows. K/V tiles 64x128 fp16,
// cp.async double-buffered. Row stride 136 fp16 (272B) -> conflict-free ldsm.
// ===========================================================================
#define VRS     136
#define FT_TILE (64 * VRS * 2)          // 17408 B
#define FSM_KV0 FT_TILE                 // after Q tile
#define FLASH_SMEM (FT_TILE * 5)        // Q + 2 stages x (K,V) = 87040 B

__global__ __launch_bounds__(128, 1) void flash_hmma_kernel(
    const __half* __restrict__ Q, const __half* __restrict__ K,
    const __half* __restrict__ V, const int* __restrict__ causal_ptr,
    __half* __restrict__ O)
{
    extern __shared__ char smem[];
    const uint32_t sb = smem_u32(smem);
    const int tid  = threadIdx.x;
    const int lane = tid & 31;
    const int wq   = tid >> 5;           // warp -> 16 q-rows
    const int qt   = blockIdx.x;
    const int h    = blockIdx.y;
    const int b    = blockIdx.z;
    const int q0   = qt * 64;
    const size_t base = (size_t)b * SEQ * DIM + (size_t)h * DH;
    const int causal = *causal_ptr;
    const int nkt = causal ? (qt + 1) : (SEQ / 64);
    const float scale = 0.08838834764831845f;

    const int g  = lane >> 3;
    const int r8 = lane & 7;
    const int r  = lane >> 2;            // 0..7
    const int cc = (lane & 3) * 2;       // 0,2,4,6

#define ISSUE_KV(KT, STG) do {                                                \
    const int kk0_ = (KT) * 64;                                               \
    const uint32_t tb_ = sb + FSM_KV0 + (STG) * 2 * FT_TILE;                  \
    _Pragma("unroll")                                                         \
    for (int t = 0; t < 8; t++) {                                             \
        int idx = tid + t * 128;                                              \
        int row = idx >> 4, c = idx & 15;                                     \
        cp16(tb_ + row * 272 + c * 16,                                        \
             K + base + (size_t)(kk0_ + row) * DIM + c * 8);                  \
        cp16(tb_ + FT_TILE + row * 272 + c * 16,                              \
             V + base + (size_t)(kk0_ + row) * DIM + c * 8);                  \
    }                                                                         \
} while (0)

    // Prologue: Q tile + KV stage 0 in group 0; KV stage 1 in group 1.
    #pragma unroll
    for (int t = 0; t < 8; t++) {
        int idx = tid + t * 128;
        int row = idx >> 4, c = idx & 15;
        cp16(sb + row * 272 + c * 16,
             Q + base + (size_t)(q0 + row) * DIM + c * 8);
    }
    ISSUE_KV(0, 0);
    CP_COMMIT();
    ISSUE_KV((1 < nkt ? 1 : nkt - 1), 1);
    CP_COMMIT();

    float m0 = -INFINITY, m1 = -INFINITY, l0 = 0.f, l1 = 0.f;
    float o[16][4];
    #pragma unroll
    for (int u = 0; u < 16; u++)
        #pragma unroll
        for (int e = 0; e < 4; e++) o[u][e] = 0.f;

    uint32_t aq[8][4];

    for (int kt = 0; kt < nkt; kt++) {
        CP_WAIT(1);
        __syncthreads();

        if (kt == 0) {
            // Preload Q fragments (reused every iteration).
            #pragma unroll
            for (int ds = 0; ds < 8; ds++) {
                uint32_t addr = sb + (uint32_t)(wq * 16 + r8 + (g & 1) * 8) * 272
                              + (uint32_t)(ds * 16 + (g >> 1) * 8) * 2;
                ldsm_x4(addr, aq[ds]);
            }
        }

        const uint32_t kbuf = sb + FSM_KV0 + (uint32_t)(kt & 1) * 2 * FT_TILE;
        const uint32_t vbuf = kbuf + FT_TILE;

        // --- Scores S = Q K^T ---
        float c[8][4];
        #pragma unroll
        for (int nt = 0; nt < 8; nt++)
            #pragma unroll
            for (int e = 0; e < 4; e++) c[nt][e] = 0.f;

        #pragma unroll
        for (int ds = 0; ds < 8; ds++) {
            uint32_t bf[4][4];
            #pragma unroll
            for (int j = 0; j < 4; j++) {
                uint32_t addr = kbuf + (uint32_t)(j * 16 + r8 + (g >> 1) * 8) * 272
                              + (uint32_t)(ds * 16 + (g & 1) * 8) * 2;
                ldsm_x4(addr, bf[j]);
            }
            #pragma unroll
            for (int nt = 0; nt < 8; nt++)
                mma_f16(c[nt], aq[ds], bf[nt >> 1][(nt & 1) * 2],
                        bf[nt >> 1][(nt & 1) * 2 + 1]);
        }

        // --- Scale + causal mask (registers) ---
        const int qrow0 = q0 + wq * 16 + r;
        const bool domask = causal && (kt == qt);
        #pragma unroll
        for (int nt = 0; nt < 8; nt++) {
            #pragma unroll
            for (int e = 0; e < 4; e++) {
                float s = c[nt][e] * scale;
                if (domask) {
                    int key = kt * 64 + nt * 8 + cc + (e & 1);
                    int qr  = qrow0 + ((e >> 1) << 3);
                    if (key > qr) s = -INFINITY;
                }
                c[nt][e] = s;
            }
        }

        // --- Online softmax (registers + shfl over 4-lane row group) ---
        float mx0 = -INFINITY, mx1 = -INFINITY;
        #pragma unroll
        for (int nt = 0; nt < 8; nt++) {
            mx0 = fmaxf(mx0, fmaxf(c[nt][0], c[nt][1]));
            mx1 = fmaxf(mx1, fmaxf(c[nt][2], c[nt][3]));
        }
        mx0 = fmaxf(mx0, __shfl_xor_sync(0xffffffffu, mx0, 1));
        mx0 = fmaxf(mx0, __shfl_xor_sync(0xffffffffu, mx0, 2));
        mx1 = fmaxf(mx1, __shfl_xor_sync(0xffffffffu, mx1, 1));
        mx1 = fmaxf(mx1, __shfl_xor_sync(0xffffffffu, mx1, 2));
        const float nm0 = fmaxf(m0, mx0), nm1 = fmaxf(m1, mx1);
        const float cor0 = __expf(m0 - nm0), cor1 = __expf(m1 - nm1);

        uint32_t ph[8][2];
        float rs0 = 0.f, rs1 = 0.f;
        #pragma unroll
        for (int nt = 0; nt < 8; nt++) {
            float p0 = __expf(c[nt][0] - nm0);
            float p1 = __expf(c[nt][1] - nm0);
            float p2 = __expf(c[nt][2] - nm1);
            float p3 = __expf(c[nt][3] - nm1);
            rs0 += p0 + p1; rs1 += p2 + p3;
            ph[nt][0] = h2pack(p0, p1);
            ph[nt][1] = h2pack(p2, p3);
        }
        rs0 += __shfl_xor_sync(0xffffffffu, rs0, 1);
        rs0 += __shfl_xor_sync(0xffffffffu, rs0, 2);
        rs1 += __shfl_xor_sync(0xffffffffu, rs1, 1);
        rs1 += __shfl_xor_sync(0xffffffffu, rs1, 2);
        l0 = l0 * cor0 + rs0;
        l1 = l1 * cor1 + rs1;
        m0 = nm0; m1 = nm1;

        #pragma unroll
        for (int u = 0; u < 16; u++) {
            o[u][0] *= cor0; o[u][1] *= cor0;
            o[u][2] *= cor1; o[u][3] *= cor1;
        }

        // --- O += P V  (A-frags from score regs, B-frags via ldsm.trans) ---
        #pragma unroll
        for (int kk = 0; kk < 4; kk++) {
            uint32_t pa[4] = { ph[2 * kk][0], ph[2 * kk][1],
                               ph[2 * kk + 1][0], ph[2 * kk + 1][1] };
            #pragma unroll
            for (int u = 0; u < 8; u++) {
                uint32_t bv[4];
                uint32_t addr = vbuf + (uint32_t)(kk * 16 + (lane & 15)) * 272
                              + (uint32_t)(u * 16 + (lane >> 4) * 8) * 2;
                ldsm_x4_t(addr, bv);
                mma_f16(o[2 * u],     pa, bv[0], bv[1]);
                mma_f16(o[2 * u + 1], pa, bv[2], bv[3]);
            }
        }

        __syncthreads();
        {
            int nx = kt + 2;
            if (nx >= nkt) nx = nkt - 1;
            ISSUE_KV(nx, kt & 1);
        }
        CP_COMMIT();
    }

    // --- Epilogue: normalize, write fp16 ---
    const float inv0 = 1.f / l0, inv1 = 1.f / l1;
    const int row0 = q0 + wq * 16 + r;
    #pragma unroll
    for (int u = 0; u < 16; u++) {
        int col = u * 8 + cc;
        *(uint32_t*)&O[base + (size_t)row0 * DIM + col] =
            h2pack(o[u][0] * inv0, o[u][1] * inv0);
        *(uint32_t*)&O[base + (size_t)(row0 + 8) * DIM + col] =
            h2pack(o[u][2] * inv1, o[u][3] * inv1);
    }
#undef ISSUE_KV
}

// ===========================================================================
extern "C" void kernel_launch(void* const* d_in, const int* in_sizes, int n_in,
                              void* d_out, int out_size)
{
    const float* q      = (const float*)d_in[0];
    const float* k      = (const float*)d_in[1];
    const float* v      = (const float*)d_in[2];
    const float* Wq     = (const float*)d_in[3];
    const float* bq     = (const float*)d_in[4];
    const float* Wk     = (const float*)d_in[5];
    const float* bk     = (const float*)d_in[6];
    const float* Wv     = (const float*)d_in[7];
    const float* bv     = (const float*)d_in[8];
    const float* Wo     = (const float*)d_in[9];
    const float* bo     = (const float*)d_in[10];
    const int*   causal = (const int*)d_in[11];
    float* out = (float*)d_out;

    __half *hQ, *hK, *hV, *hA, *hW;
    cudaGetSymbolAddress((void**)&hQ, g_hQ);
    cudaGetSymbolAddress((void**)&hK, g_hK);
    cudaGetSymbolAddress((void**)&hV, g_hV);
    cudaGetSymbolAddress((void**)&hA, g_hA);
    cudaGetSymbolAddress((void**)&hW, g_hW);

    const int M = BATCH * SEQ;                   // 4096
    const int n4x = M * DIM / 4;
    const int n4w = DIM * DIM / 4;
    dim3 ggrid(DIM / 128, M / 128);              // (16, 32)

    cudaFuncSetAttribute(gemm_f16_kernel,
                         cudaFuncAttributeMaxDynamicSharedMemorySize, GEMM_SMEM);
    cudaFuncSetAttribute(flash_hmma_kernel,
                         cudaFuncAttributeMaxDynamicSharedMemorySize, FLASH_SMEM);

    // Projections (fp16 out for flash)
    cvt_kernel<<<n4x / 256, 256>>>(q, hA, n4x);
    cvt_kernel<<<n4w / 256, 256>>>(Wq, hW, n4w);
    gemm_f16_kernel<<<ggrid, 256, GEMM_SMEM>>>(hA, hW, bq, nullptr, hQ, 1, M, DIM, DIM);
    cvt_kernel<<<n4x / 256, 256>>>(k, hA, n4x);
    cvt_kernel<<<n4w / 256, 256>>>(Wk, hW, n4w);
    gemm_f16_kernel<<<ggrid, 256, GEMM_SMEM>>>(hA, hW, bk, nullptr, hK, 1, M, DIM, DIM);
    cvt_kernel<<<n4x / 256, 256>>>(v, hA, n4x);
    cvt_kernel<<<n4w / 256, 256>>>(Wv, hW, n4w);
    gemm_f16_kernel<<<ggrid, 256, GEMM_SMEM>>>(hA, hW, bv, nullptr, hV, 1, M, DIM, DIM);

    // Attention (fp16 HMMA), writes fp16 into hA
    dim3 fgrid(SEQ / 64, NH, BATCH);             // (32, 16, 2)
    flash_hmma_kernel<<<fgrid, 128, FLASH_SMEM>>>(hQ, hK, hV, causal, hA);

    // Output projection (fp32 out)
    cvt_kernel<<<n4w / 256, 256>>>(Wo, hW, n4w);
    gemm_f16_kernel<<<ggrid, 256, GEMM_SMEM>>>(hA, hW, bo, out, nullptr, 0, M, DIM, DIM);
}

// round 12
// speedup vs baseline: 11.3117x; 1.1888x over previous
#include <cuda_runtime.h>
#include <cuda_fp16.h>
#include <math.h>
#include <stdint.h>

#define BATCH 2
#define SEQ   2048
#define DIM   2048
#define NH    16
#define DH    128

// Scratch — __device__ globals per allocation rules.
__device__ __half g_hI0[BATCH * SEQ * DIM];   // converted q
__device__ __half g_hI1[BATCH * SEQ * DIM];   // converted k
__device__ __half g_hI2[BATCH * SEQ * DIM];   // converted v
__device__ __half g_hQ[BATCH * SEQ * DIM];
__device__ __half g_hK[BATCH * SEQ * DIM];
__device__ __half g_hV[BATCH * SEQ * DIM];
__device__ __half g_hO[BATCH * SEQ * DIM];    // attention out
__device__ __half g_hW0[DIM * DIM];
__device__ __half g_hW1[DIM * DIM];
__device__ __half g_hW2[DIM * DIM];

// ===========================================================================
// Helpers
// ===========================================================================
__device__ __forceinline__ uint32_t smem_u32(const void* p) {
    uint32_t a;
    asm("{ .reg .u64 t; cvta.to.shared.u64 t, %1; cvt.u32.u64 %0, t; }"
        : "=r"(a) : "l"(p));
    return a;
}

__device__ __forceinline__ void ldsm_x4(uint32_t addr, uint32_t r[4]) {
    asm volatile("ldmatrix.sync.aligned.m8n8.x4.shared.b16 {%0,%1,%2,%3}, [%4];"
                 : "=r"(r[0]), "=r"(r[1]), "=r"(r[2]), "=r"(r[3]) : "r"(addr));
}
__device__ __forceinline__ void ldsm_x4_t(uint32_t addr, uint32_t r[4]) {
    asm volatile("ldmatrix.sync.aligned.m8n8.x4.trans.shared.b16 {%0,%1,%2,%3}, [%4];"
                 : "=r"(r[0]), "=r"(r[1]), "=r"(r[2]), "=r"(r[3]) : "r"(addr));
}

__device__ __forceinline__ void mma_f16(float c[4], const uint32_t a[4],
                                        const uint32_t b0, const uint32_t b1) {
    asm volatile(
        "mma.sync.aligned.m16n8k16.row.col.f32.f16.f16.f32 "
        "{%0,%1,%2,%3}, {%4,%5,%6,%7}, {%8,%9}, {%0,%1,%2,%3};"
        : "+f"(c[0]), "+f"(c[1]), "+f"(c[2]), "+f"(c[3])
        : "r"(a[0]), "r"(a[1]), "r"(a[2]), "r"(a[3]), "r"(b0), "r"(b1));
}

__device__ __forceinline__ void cp16(uint32_t saddr, const void* gaddr) {
    asm volatile("cp.async.ca.shared.global [%0], [%1], 16;"
                 :: "r"(saddr), "l"(gaddr));
}
#define CP_COMMIT() asm volatile("cp.async.commit_group;" ::: "memory")
#define CP_WAIT(n)  asm volatile("cp.async.wait_group %0;" :: "n"(n) : "memory")

__device__ __forceinline__ uint32_t h2pack(float a, float b) {
    __half2 h = __floats2half2_rn(a, b);
    return *(uint32_t*)&h;
}

// ===========================================================================
// Conversion: fp32 -> fp16 (rn), up to 3 tensors via blockIdx.z
// ===========================================================================
__global__ __launch_bounds__(256) void cvt3_kernel(
    const float* __restrict__ i0, const float* __restrict__ i1,
    const float* __restrict__ i2,
    __half* __restrict__ o0, __half* __restrict__ o1, __half* __restrict__ o2,
    int n4)
{
    int i = blockIdx.x * blockDim.x + threadIdx.x;
    if (i >= n4) return;
    const int z = blockIdx.z;
    const float* in  = (z == 0) ? i0 : (z == 1) ? i1 : i2;
    __half* out      = (z == 0) ? o0 : (z == 1) ? o1 : o2;
    float4 v = ((const float4*)in)[i];
    uint2 o;
    o.x = h2pack(v.x, v.y);
    o.y = h2pack(v.z, v.w);
    ((uint2*)out)[i] = o;
}

// ===========================================================================
// fp16 HMMA GEMM: C[M,N] = A[M,K] @ W[N,K]^T + bias
// CTA 128x128, BK=32, 4 warps (2x2), warp tile 64x64.
// blockIdx.z selects one of up to 3 (A, W, bias, C) problem instances.
// ===========================================================================
#define GRS    40
#define GTILE  (128 * GRS * 2)
#define GSTAGE (2 * GTILE)
#define NSTG   3
#define GEMM_SMEM (NSTG * GSTAGE)       // 61440 B

__global__ __launch_bounds__(128, 2) void gemm_f16_kernel(
    const __half* __restrict__ A0, const __half* __restrict__ A1,
    const __half* __restrict__ A2,
    const __half* __restrict__ W0, const __half* __restrict__ W1,
    const __half* __restrict__ W2,
    const float* __restrict__ b0, const float* __restrict__ b1,
    const float* __restrict__ b2,
    float* __restrict__ Cf,
    __half* __restrict__ H0, __half* __restrict__ H1, __half* __restrict__ H2,
    int outhalf, int M, int N, int Kd)
{
    extern __shared__ char smem[];
    const uint32_t sbase = smem_u32(smem);
    const int z = blockIdx.z;
    const __half* Ah   = (z == 0) ? A0 : (z == 1) ? A1 : A2;
    const __half* Wh   = (z == 0) ? W0 : (z == 1) ? W1 : W2;
    const float*  bias = (z == 0) ? b0 : (z == 1) ? b1 : b2;
    __half*       Ch   = (z == 0) ? H0 : (z == 1) ? H1 : H2;

    const int tid  = threadIdx.x;
    const int wid  = tid >> 5;
    const int lane = tid & 31;
    const int wm   = wid >> 1;           // 0..1
    const int wn   = wid & 1;            // 0..1
    const int bm   = blockIdx.y * 128;
    const int bn   = blockIdx.x * 128;

    float acc[4][8][4];
    #pragma unroll
    for (int i = 0; i < 4; i++)
        #pragma unroll
        for (int j = 0; j < 8; j++)
            #pragma unroll
            for (int e = 0; e < 4; e++) acc[i][j][e] = 0.f;

    // cp.async: per stage, tiles A + W, each 128 rows x 32 cols fp16.
    // 512 chunks of 16B per tile, 128 threads -> 4 rows per thread per tile.
    const int crow = tid >> 2;           // 0..31 (+t*32)
    const int ccol = tid & 3;            // 16B chunk in row

#define ISSUE_STAGE(CH, STG) do {                                             \
    const int k0_ = (CH) * 32;                                                \
    const uint32_t sb_ = sbase + (STG) * GSTAGE;                              \
    _Pragma("unroll")                                                         \
    for (int t = 0; t < 4; t++) {                                             \
        const int row_ = crow + t * 32;                                       \
        const uint32_t so_ = (uint32_t)(row_ * 80 + ccol * 16);               \
        cp16(sb_ + so_,         Ah + (size_t)(bm + row_) * Kd + k0_ + ccol * 8); \
        cp16(sb_ + GTILE + so_, Wh + (size_t)(bn + row_) * Kd + k0_ + ccol * 8); \
    }                                                                         \
} while (0)

    #pragma unroll
    for (int s = 0; s < NSTG; s++) { ISSUE_STAGE(s, s); CP_COMMIT(); }

    const int g  = lane >> 3;
    const int r8 = lane & 7;
    const int nchunk = Kd / 32;

    for (int ch = 0; ch < nchunk; ch++) {
        CP_WAIT(NSTG - 1);
        __syncthreads();
        const uint32_t buf = sbase + (ch % NSTG) * GSTAGE;

        #pragma unroll
        for (int ks = 0; ks < 2; ks++) {
            const int k0 = ks * 16;
            uint32_t af[4][4];
            #pragma unroll
            for (int mt = 0; mt < 4; mt++) {
                int row = wm * 64 + mt * 16 + r8 + (g & 1) * 8;
                uint32_t off = (uint32_t)(row * GRS + k0 + (g >> 1) * 8) * 2;
                ldsm_x4(buf + off, af[mt]);
            }
            uint32_t bf[4][4];
            #pragma unroll
            for (int np = 0; np < 4; np++) {
                int nrow = wn * 64 + np * 16 + r8 + (g >> 1) * 8;
                uint32_t off = (uint32_t)(nrow * GRS + k0 + (g & 1) * 8) * 2;
                ldsm_x4(buf + GTILE + off, bf[np]);
            }
            #pragma unroll
            for (int mt = 0; mt < 4; mt++) {
                #pragma unroll
                for (int nt = 0; nt < 8; nt++) {
                    const int np = nt >> 1, hf = (nt & 1) * 2;
                    mma_f16(acc[mt][nt], af[mt], bf[np][hf], bf[np][hf + 1]);
                }
            }
        }
        __syncthreads();
        if (ch + NSTG < nchunk) ISSUE_STAGE(ch + NSTG, ch % NSTG);
        CP_COMMIT();
    }

    // Epilogue.
    #pragma unroll
    for (int nt = 0; nt < 8; nt++) {
        const int gcol = bn + wn * 64 + nt * 8 + (lane & 3) * 2;
        const float2 bv = *(const float2*)&bias[gcol];
        #pragma unroll
        for (int mt = 0; mt < 4; mt++) {
            const int grow = bm + wm * 64 + mt * 16 + (lane >> 2);
            float x0 = acc[mt][nt][0] + bv.x;
            float y0 = acc[mt][nt][1] + bv.y;
            float x1 = acc[mt][nt][2] + bv.x;
            float y1 = acc[mt][nt][3] + bv.y;
            if (outhalf) {
                *(uint32_t*)&Ch[(size_t)grow * N + gcol] = h2pack(x0, y0);
                *(uint32_t*)&Ch[(size_t)(grow + 8) * N + gcol] = h2pack(x1, y1);
            } else {
                float2 o0 = {x0, y0}, o1 = {x1, y1};
                *(float2*)&Cf[(size_t)grow * N + gcol] = o0;
                *(float2*)&Cf[(size_t)(grow + 8) * N + gcol] = o1;
            }
        }
    }
#undef ISSUE_STAGE
}

// ===========================================================================
// Flash attention, fp16 HMMA, P-in-registers (unchanged from round 11).
// ===========================================================================
#define VRS     136
#define FT_TILE (64 * VRS * 2)
#define FSM_KV0 FT_TILE
#define FLASH_SMEM (FT_TILE * 5)        // 87040 B

__global__ __launch_bounds__(128, 1) void flash_hmma_kernel(
    const __half* __restrict__ Q, const __half* __restrict__ K,
    const __half* __restrict__ V, const int* __restrict__ causal_ptr,
    __half* __restrict__ O)
{
    extern __shared__ char smem[];
    const uint32_t sb = smem_u32(smem);
    const int tid  = threadIdx.x;
    const int lane = tid & 31;
    const int wq   = tid >> 5;
    const int qt   = blockIdx.x;
    const int h    = blockIdx.y;
    const int b    = blockIdx.z;
    const int q0   = qt * 64;
    const size_t base = (size_t)b * SEQ * DIM + (size_t)h * DH;
    const int causal = *causal_ptr;
    const int nkt = causal ? (qt + 1) : (SEQ / 64);
    const float scale = 0.08838834764831845f;

    const int g  = lane >> 3;
    const int r8 = lane & 7;
    const int r  = lane >> 2;
    const int cc = (lane & 3) * 2;

#define ISSUE_KV(KT, STG) do {                                                \
    const int kk0_ = (KT) * 64;                                               \
    const uint32_t tb_ = sb + FSM_KV0 + (STG) * 2 * FT_TILE;                  \
    _Pragma("unroll")                                                         \
    for (int t = 0; t < 8; t++) {                                             \
        int idx = tid + t * 128;                                              \
        int row = idx >> 4, c = idx & 15;                                     \
        cp16(tb_ + row * 272 + c * 16,                                        \
             K + base + (size_t)(kk0_ + row) * DIM + c * 8);                  \
        cp16(tb_ + FT_TILE + row * 272 + c * 16,                              \
             V + base + (size_t)(kk0_ + row) * DIM + c * 8);                  \
    }                                                                         \
} while (0)

    #pragma unroll
    for (int t = 0; t < 8; t++) {
        int idx = tid + t * 128;
        int row = idx >> 4, c = idx & 15;
        cp16(sb + row * 272 + c * 16,
             Q + base + (size_t)(q0 + row) * DIM + c * 8);
    }
    ISSUE_KV(0, 0);
    CP_COMMIT();
    ISSUE_KV((1 < nkt ? 1 : nkt - 1), 1);
    CP_COMMIT();

    float m0 = -INFINITY, m1 = -INFINITY, l0 = 0.f, l1 = 0.f;
    float o[16][4];
    #pragma unroll
    for (int u = 0; u < 16; u++)
        #pragma unroll
        for (int e = 0; e < 4; e++) o[u][e] = 0.f;

    uint32_t aq[8][4];

    for (int kt = 0; kt < nkt; kt++) {
        CP_WAIT(1);
        __syncthreads();

        if (kt == 0) {
            #pragma unroll
            for (int ds = 0; ds < 8; ds++) {
                uint32_t addr = sb + (uint32_t)(wq * 16 + r8 + (g & 1) * 8) * 272
                              + (uint32_t)(ds * 16 + (g >> 1) * 8) * 2;
                ldsm_x4(addr, aq[ds]);
            }
        }

        const uint32_t kbuf = sb + FSM_KV0 + (uint32_t)(kt & 1) * 2 * FT_TILE;
        const uint32_t vbuf = kbuf + FT_TILE;

        float c[8][4];
        #pragma unroll
        for (int nt = 0; nt < 8; nt++)
            #pragma unroll
            for (int e = 0; e < 4; e++) c[nt][e] = 0.f;

        #pragma unroll
        for (int ds = 0; ds < 8; ds++) {
            uint32_t bf[4][4];
            #pragma unroll
            for (int j = 0; j < 4; j++) {
                uint32_t addr = kbuf + (uint32_t)(j * 16 + r8 + (g >> 1) * 8) * 272
                              + (uint32_t)(ds * 16 + (g & 1) * 8) * 2;
                ldsm_x4(addr, bf[j]);
            }
            #pragma unroll
            for (int nt = 0; nt < 8; nt++)
                mma_f16(c[nt], aq[ds], bf[nt >> 1][(nt & 1) * 2],
                        bf[nt >> 1][(nt & 1) * 2 + 1]);
        }

        const int qrow0 = q0 + wq * 16 + r;
        const bool domask = causal && (kt == qt);
        #pragma unroll
        for (int nt = 0; nt < 8; nt++) {
            #pragma unroll
            for (int e = 0; e < 4; e++) {
                float s = c[nt][e] * scale;
                if (domask) {
                    int key = kt * 64 + nt * 8 + cc + (e & 1);
                    int qr  = qrow0 + ((e >> 1) << 3);
                    if (key > qr) s = -INFINITY;
                }
                c[nt][e] = s;
            }
        }

        float mx0 = -INFINITY, mx1 = -INFINITY;
        #pragma unroll
        for (int nt = 0; nt < 8; nt++) {
            mx0 = fmaxf(mx0, fmaxf(c[nt][0], c[nt][1]));
            mx1 = fmaxf(mx1, fmaxf(c[nt][2], c[nt][3]));
        }
        mx0 = fmaxf(mx0, __shfl_xor_sync(0xffffffffu, mx0, 1));
        mx0 = fmaxf(mx0, __shfl_xor_sync(0xffffffffu, mx0, 2));
        mx1 = fmaxf(mx1, __shfl_xor_sync(0xffffffffu, mx1, 1));
        mx1 = fmaxf(mx1, __shfl_xor_sync(0xffffffffu, mx1, 2));
        const float nm0 = fmaxf(m0, mx0), nm1 = fmaxf(m1, mx1);
        const float cor0 = __expf(m0 - nm0), cor1 = __expf(m1 - nm1);

        uint32_t ph[8][2];
        float rs0 = 0.f, rs1 = 0.f;
        #pragma unroll
        for (int nt = 0; nt < 8; nt++) {
            float p0 = __expf(c[nt][0] - nm0);
            float p1 = __expf(c[nt][1] - nm0);
            float p2 = __expf(c[nt][2] - nm1);
            float p3 = __expf(c[nt][3] - nm1);
            rs0 += p0 + p1; rs1 += p2 + p3;
            ph[nt][0] = h2pack(p0, p1);
            ph[nt][1] = h2pack(p2, p3);
        }
        rs0 += __shfl_xor_sync(0xffffffffu, rs0, 1);
        rs0 += __shfl_xor_sync(0xffffffffu, rs0, 2);
        rs1 += __shfl_xor_sync(0xffffffffu, rs1, 1);
        rs1 += __shfl_xor_sync(0xffffffffu, rs1, 2);
        l0 = l0 * cor0 + rs0;
        l1 = l1 * cor1 + rs1;
        m0 = nm0; m1 = nm1;

        #pragma unroll
        for (int u = 0; u < 16; u++) {
            o[u][0] *= cor0; o[u][1] *= cor0;
            o[u][2] *= cor1; o[u][3] *= cor1;
        }

        #pragma unroll
        for (int kk = 0; kk < 4; kk++) {
            uint32_t pa[4] = { ph[2 * kk][0], ph[2 * kk][1],
                               ph[2 * kk + 1][0], ph[2 * kk + 1][1] };
            #pragma unroll
            for (int u = 0; u < 8; u++) {
                uint32_t bv[4];
                uint32_t addr = vbuf + (uint32_t)(kk * 16 + (lane & 15)) * 272
                              + (uint32_t)(u * 16 + (lane >> 4) * 8) * 2;
                ldsm_x4_t(addr, bv);
                mma_f16(o[2 * u],     pa, bv[0], bv[1]);
                mma_f16(o[2 * u + 1], pa, bv[2], bv[3]);
            }
        }

        __syncthreads();
        {
            int nx = kt + 2;
            if (nx >= nkt) nx = nkt - 1;
            ISSUE_KV(nx, kt & 1);
        }
        CP_COMMIT();
    }

    const float inv0 = 1.f / l0, inv1 = 1.f / l1;
    const int row0 = q0 + wq * 16 + r;
    #pragma unroll
    for (int u = 0; u < 16; u++) {
        int col = u * 8 + cc;
        *(uint32_t*)&O[base + (size_t)row0 * DIM + col] =
            h2pack(o[u][0] * inv0, o[u][1] * inv0);
        *(uint32_t*)&O[base + (size_t)(row0 + 8) * DIM + col] =
            h2pack(o[u][2] * inv1, o[u][3] * inv1);
    }
#undef ISSUE_KV
}

// ===========================================================================
extern "C" void kernel_launch(void* const* d_in, const int* in_sizes, int n_in,
                              void* d_out, int out_size)
{
    const float* q      = (const float*)d_in[0];
    const float* k      = (const float*)d_in[1];
    const float* v      = (const float*)d_in[2];
    const float* Wq     = (const float*)d_in[3];
    const float* bq     = (const float*)d_in[4];
    const float* Wk     = (const float*)d_in[5];
    const float* bk     = (const float*)d_in[6];
    const float* Wv     = (const float*)d_in[7];
    const float* bv     = (const float*)d_in[8];
    const float* Wo     = (const float*)d_in[9];
    const float* bo     = (const float*)d_in[10];
    const int*   causal = (const int*)d_in[11];
    float* out = (float*)d_out;

    __half *hI0, *hI1, *hI2, *hQ, *hK, *hV, *hO, *hW0, *hW1, *hW2;
    cudaGetSymbolAddress((void**)&hI0, g_hI0);
    cudaGetSymbolAddress((void**)&hI1, g_hI1);
    cudaGetSymbolAddress((void**)&hI2, g_hI2);
    cudaGetSymbolAddress((void**)&hQ,  g_hQ);
    cudaGetSymbolAddress((void**)&hK,  g_hK);
    cudaGetSymbolAddress((void**)&hV,  g_hV);
    cudaGetSymbolAddress((void**)&hO,  g_hO);
    cudaGetSymbolAddress((void**)&hW0, g_hW0);
    cudaGetSymbolAddress((void**)&hW1, g_hW1);
    cudaGetSymbolAddress((void**)&hW2, g_hW2);

    const int M = BATCH * SEQ;                   // 4096
    const int n4x = M * DIM / 4;
    const int n4w = DIM * DIM / 4;

    cudaFuncSetAttribute(gemm_f16_kernel,
                         cudaFuncAttributeMaxDynamicSharedMemorySize, GEMM_SMEM);
    cudaFuncSetAttribute(flash_hmma_kernel,
                         cudaFuncAttributeMaxDynamicSharedMemorySize, FLASH_SMEM);

    // Convert q,k,v (one launch) and Wq,Wk,Wv (one launch).
    {
        dim3 cg(n4x / 256, 1, 3);
        cvt3_kernel<<<cg, 256>>>(q, k, v, hI0, hI1, hI2, n4x);
    }
    {
        dim3 cg(n4w / 256, 1, 3);
        cvt3_kernel<<<cg, 256>>>(Wq, Wk, Wv, hW0, hW1, hW2, n4w);
    }

    // Three projections in one launch (fp16 out).
    {
        dim3 gg(DIM / 128, M / 128, 3);          // (16, 32, 3)
        gemm_f16_kernel<<<gg, 128, GEMM_SMEM>>>(
            hI0, hI1, hI2, hW0, hW1, hW2, bq, bk, bv,
            nullptr, hQ, hK, hV, 1, M, DIM, DIM);
    }

    // Attention (fp16 HMMA), writes fp16 into hO.
    {
        dim3 fg(SEQ / 64, NH, BATCH);            // (32, 16, 2)
        flash_hmma_kernel<<<fg, 128, FLASH_SMEM>>>(hQ, hK, hV, causal, hO);
    }

    // Convert Wo, then output projection (fp32 out).
    {
        dim3 cg(n4w / 256, 1, 1);
        cvt3_kernel<<<cg, 256>>>(Wo, Wo, Wo, hW0, hW0, hW0, n4w);
    }
    {
        dim3 gg(DIM / 128, M / 128, 1);
        gemm_f16_kernel<<<gg, 128, GEMM_SMEM>>>(
            hO, hO, hO, hW0, hW0, hW0, bo, bo, bo,
            out, nullptr, nullptr, nullptr, 0, M, DIM, DIM);
    }
}